// round 9
// baseline (speedup 1.0000x reference)
#include <cuda_runtime.h>
#include <cuda_bf16.h>
#include <cstdint>

// B=4, T=2048, D=1024, H=16, HD=64
#define BB 4
#define TT 2048
#define DD 1024
#define HH 16
#define HDIM 64
#define MROWS (BB * TT)          // 8192
#define QKV_COLS (3 * DD)        // 3072

// ---------------- scratch (__device__ globals; allocation-free) -------------
__device__ __nv_bfloat16 g_xh[(size_t)MROWS * DD];
__device__ __nv_bfloat16 g_xl[(size_t)MROWS * DD];
__device__ __nv_bfloat16 g_wqh[(size_t)QKV_COLS * DD];
__device__ __nv_bfloat16 g_wql[(size_t)QKV_COLS * DD];
__device__ __nv_bfloat16 g_wph[(size_t)DD * DD];
__device__ __nv_bfloat16 g_wpl[(size_t)DD * DD];
__device__ __nv_bfloat16 g_qkvh[(size_t)MROWS * QKV_COLS];
__device__ __nv_bfloat16 g_qkvl[(size_t)MROWS * QKV_COLS];
__device__ __nv_bfloat16 g_ah[(size_t)MROWS * DD];
__device__ __nv_bfloat16 g_al[(size_t)MROWS * DD];

// ---------------- helpers ---------------------------------------------------
__device__ __forceinline__ void mma_bf16(float* c, const uint32_t* a, const uint32_t* b) {
    asm volatile(
        "mma.sync.aligned.m16n8k16.row.col.f32.bf16.bf16.f32 "
        "{%0,%1,%2,%3},{%4,%5,%6,%7},{%8,%9},{%0,%1,%2,%3};"
        : "+f"(c[0]), "+f"(c[1]), "+f"(c[2]), "+f"(c[3])
        : "r"(a[0]), "r"(a[1]), "r"(a[2]), "r"(a[3]), "r"(b[0]), "r"(b[1]));
}

__device__ __forceinline__ void cp16(void* smem_dst, const void* gsrc) {
    uint32_t s = (uint32_t)__cvta_generic_to_shared(smem_dst);
    asm volatile("cp.async.ca.shared.global [%0], [%1], 16;" :: "r"(s), "l"(gsrc));
}
__device__ __forceinline__ void cp_commit() { asm volatile("cp.async.commit_group;"); }
template <int N> __device__ __forceinline__ void cp_wait() {
    asm volatile("cp.async.wait_group %0;" :: "n"(N));
}
__device__ __forceinline__ uint32_t lds32(const __nv_bfloat16* p) {
    return *reinterpret_cast<const uint32_t*>(p);
}

// ---------------- split fp32 -> (hi, lo) bf16 -------------------------------
__global__ void split_kernel(const float* __restrict__ x,
                             __nv_bfloat16* __restrict__ h,
                             __nv_bfloat16* __restrict__ l, int n4)
{
    int i = blockIdx.x * blockDim.x + threadIdx.x;
    if (i >= n4) return;
    float4 v = reinterpret_cast<const float4*>(x)[i];
    float vv[4] = {v.x, v.y, v.z, v.w};
    __nv_bfloat16 hh[4], ll[4];
#pragma unroll
    for (int k = 0; k < 4; k++) {
        hh[k] = __float2bfloat16(vv[k]);
        ll[k] = __float2bfloat16(vv[k] - __bfloat162float(hh[k]));
    }
    reinterpret_cast<uint2*>(h)[i] = *reinterpret_cast<uint2*>(hh);
    reinterpret_cast<uint2*>(l)[i] = *reinterpret_cast<uint2*>(ll);
}

// ---------------- split-bf16 GEMM: C[M,N] = A @ B^T (+bias) -----------------
// 128x128 tile, BK=32, 256 thr, 8 warps (4m x 2n), warp 32x64. cp.async x2.
// MMA issue: term-batched over (m, n-group of 4) -> RAW reuse distance = 8.
#define GST 40                      // smem row stride (bf16)
#define GTILE (128 * GST)           // 5120 bf16
#define G_AH 0
#define G_AL GTILE
#define G_BH (2 * GTILE)
#define G_BL (3 * GTILE)
#define G_STAGE (4 * GTILE)         // 20480 bf16
#define GEMM_SMEM (2 * G_STAGE * 2) // 81920 bytes

template <bool SPLIT_OUT, bool HAS_BIAS>
__global__ __launch_bounds__(256, 2) void gemm_sp(
    const __nv_bfloat16* __restrict__ Ahg, const __nv_bfloat16* __restrict__ Alg,
    const __nv_bfloat16* __restrict__ Bhg, const __nv_bfloat16* __restrict__ Blg,
    const float* __restrict__ bias,
    float* __restrict__ Cf,
    __nv_bfloat16* __restrict__ Chg, __nv_bfloat16* __restrict__ Clg,
    int M, int N, int K)
{
    extern __shared__ __nv_bfloat16 sm[];
    const int tid  = threadIdx.x;
    const int lane = tid & 31;
    const int wid  = tid >> 5;
    const int g    = lane >> 2;
    const int q    = lane & 3;
    const int m0   = (wid & 3) * 32;
    const int n0   = (wid >> 2) * 64;
    const int bRow = blockIdx.y * 128;
    const int bCol = blockIdx.x * 128;

    const int lrow = tid >> 2;          // 0..63
    const int lc8  = (tid & 3) * 8;     // 0,8,16,24

    float c[2][8][4];
#pragma unroll
    for (int m = 0; m < 2; m++)
#pragma unroll
        for (int n = 0; n < 8; n++)
#pragma unroll
            for (int r = 0; r < 4; r++) c[m][n][r] = 0.f;

    const int NT = K / 32;

    auto issue = [&](int t, int stg) {
        const int k0 = t * 32;
        __nv_bfloat16* s = sm + stg * G_STAGE;
        const size_t aoff0 = (size_t)(bRow + lrow) * K + k0 + lc8;
        const size_t aoff1 = (size_t)(bRow + lrow + 64) * K + k0 + lc8;
        const size_t boff0 = (size_t)(bCol + lrow) * K + k0 + lc8;
        const size_t boff1 = (size_t)(bCol + lrow + 64) * K + k0 + lc8;
        cp16(s + G_AH + lrow * GST + lc8,        Ahg + aoff0);
        cp16(s + G_AH + (lrow + 64) * GST + lc8, Ahg + aoff1);
        cp16(s + G_AL + lrow * GST + lc8,        Alg + aoff0);
        cp16(s + G_AL + (lrow + 64) * GST + lc8, Alg + aoff1);
        cp16(s + G_BH + lrow * GST + lc8,        Bhg + boff0);
        cp16(s + G_BH + (lrow + 64) * GST + lc8, Bhg + boff1);
        cp16(s + G_BL + lrow * GST + lc8,        Blg + boff0);
        cp16(s + G_BL + (lrow + 64) * GST + lc8, Blg + boff1);
    };

    issue(0, 0);
    cp_commit();

    for (int t = 0; t < NT; ++t) {
        if (t + 1 < NT) { issue(t + 1, (t + 1) & 1); cp_commit(); cp_wait<1>(); }
        else            { cp_wait<0>(); }
        __syncthreads();

        const __nv_bfloat16* s = sm + (t & 1) * G_STAGE;
#pragma unroll
        for (int kk = 0; kk < 2; kk++) {
            uint32_t ah[2][4], al[2][4];
#pragma unroll
            for (int m = 0; m < 2; m++) {
                const int base = (m0 + m * 16 + g) * GST + kk * 16 + 2 * q;
                ah[m][0] = lds32(s + G_AH + base);
                ah[m][1] = lds32(s + G_AH + base + 8 * GST);
                ah[m][2] = lds32(s + G_AH + base + 8);
                ah[m][3] = lds32(s + G_AH + base + 8 * GST + 8);
                al[m][0] = lds32(s + G_AL + base);
                al[m][1] = lds32(s + G_AL + base + 8 * GST);
                al[m][2] = lds32(s + G_AL + base + 8);
                al[m][3] = lds32(s + G_AL + base + 8 * GST + 8);
            }
#pragma unroll
            for (int nh = 0; nh < 2; nh++) {
                uint32_t bh[4][2], bl[4][2];
#pragma unroll
                for (int n = 0; n < 4; n++) {
                    const int bb = (n0 + (nh * 4 + n) * 8 + g) * GST + kk * 16 + 2 * q;
                    bh[n][0] = lds32(s + G_BH + bb);
                    bh[n][1] = lds32(s + G_BH + bb + 8);
                    bl[n][0] = lds32(s + G_BL + bb);
                    bl[n][1] = lds32(s + G_BL + bb + 8);
                }
                // term-batched: 8 independent MMAs between accumulator reuses
#pragma unroll
                for (int n = 0; n < 4; n++)
#pragma unroll
                    for (int m = 0; m < 2; m++)
                        mma_bf16(c[m][nh * 4 + n], ah[m], bh[n]);
#pragma unroll
                for (int n = 0; n < 4; n++)
#pragma unroll
                    for (int m = 0; m < 2; m++)
                        mma_bf16(c[m][nh * 4 + n], al[m], bh[n]);
#pragma unroll
                for (int n = 0; n < 4; n++)
#pragma unroll
                    for (int m = 0; m < 2; m++)
                        mma_bf16(c[m][nh * 4 + n], ah[m], bl[n]);
            }
        }
        __syncthreads();
    }

    // epilogue
#pragma unroll
    for (int m = 0; m < 2; m++) {
#pragma unroll
        for (int n = 0; n < 8; n++) {
            const int row = bRow + m0 + m * 16 + g;
            const int col = bCol + n0 + n * 8 + 2 * q;
#pragma unroll
            for (int half = 0; half < 2; half++) {
                const int r = row + half * 8;
                float v0 = c[m][n][half * 2 + 0];
                float v1 = c[m][n][half * 2 + 1];
                if (HAS_BIAS) { v0 += bias[col]; v1 += bias[col + 1]; }
                if (SPLIT_OUT) {
                    __nv_bfloat16 h0 = __float2bfloat16(v0);
                    __nv_bfloat16 h1 = __float2bfloat16(v1);
                    __nv_bfloat16 l0 = __float2bfloat16(v0 - __bfloat162float(h0));
                    __nv_bfloat16 l1 = __float2bfloat16(v1 - __bfloat162float(h1));
                    __nv_bfloat162 hp; hp.x = h0; hp.y = h1;
                    __nv_bfloat162 lp; lp.x = l0; lp.y = l1;
                    *reinterpret_cast<__nv_bfloat162*>(&Chg[(size_t)r * N + col]) = hp;
                    *reinterpret_cast<__nv_bfloat162*>(&Clg[(size_t)r * N + col]) = lp;
                } else {
                    float2 w; w.x = v0; w.y = v1;
                    *reinterpret_cast<float2*>(&Cf[(size_t)r * N + col]) = w;
                }
            }
        }
    }
}

// ---------------- split-bf16 causal flash attention --------------------------
// 256 thr (8 warps), 128-query x 64-key tiles. warp w: rows 16w..16w+15.
// MMA issue: term-batched over j-groups of 4 -> RAW reuse distance = 4.
#define FST 72
#define FQ  (128 * FST)              // 9216 elems
#define FK  (64 * FST)               // 4608 elems
#define F_QH 0
#define F_QL FQ
#define F_KH (2 * FQ)
#define F_KL (2 * FQ + FK)
#define F_VH (2 * FQ + 2 * FK)
#define F_VL (2 * FQ + 3 * FK)
#define F_PH (2 * FQ + 4 * FK)
#define F_PL (3 * FQ + 4 * FK)
#define FLASH_SMEM ((4 * FQ + 4 * FK) * 2)   // 110592 bytes

__global__ __launch_bounds__(256, 2) void flash_sp(
    const __nv_bfloat16* __restrict__ qkvh,
    const __nv_bfloat16* __restrict__ qkvl,
    __nv_bfloat16* __restrict__ Oh, __nv_bfloat16* __restrict__ Ol)
{
    extern __shared__ __nv_bfloat16 fsm[];
    __nv_bfloat16* Qh = fsm + F_QH;  __nv_bfloat16* Ql = fsm + F_QL;
    __nv_bfloat16* Kh = fsm + F_KH;  __nv_bfloat16* Kl = fsm + F_KL;
    __nv_bfloat16* Vh = fsm + F_VH;  __nv_bfloat16* Vl = fsm + F_VL;
    __nv_bfloat16* Ph = fsm + F_PH;  __nv_bfloat16* Pl = fsm + F_PL;

    const int tid  = threadIdx.x;
    const int lane = tid & 31;
    const int wid  = tid >> 5;
    const int g    = lane >> 2;
    const int q    = lane & 3;
    const int qt   = blockIdx.x;         // 128-query tile (0..15)
    const int b    = blockIdx.y >> 4;
    const int h    = blockIdx.y & 15;
    const int q0   = qt * 128;
    const int rl0  = wid * 16 + g;       // 0..127
    const int rl1  = rl0 + 8;

    // load Q (scaled by 1/8, exact power of two)
    __nv_bfloat162 sc2; sc2.x = __float2bfloat16(0.125f); sc2.y = sc2.x;
#pragma unroll
    for (int l = 0; l < 4; l++) {
        const int idx = tid + l * 256;   // 0..1023
        const int r = idx >> 3;          // 0..127
        const int c8 = (idx & 7) * 8;
        const size_t off = (size_t)(b * TT + q0 + r) * QKV_COLS + h * HDIM + c8;
        uint4 vh4 = *reinterpret_cast<const uint4*>(qkvh + off);
        uint4 vl4 = *reinterpret_cast<const uint4*>(qkvl + off);
        __nv_bfloat162* ph = reinterpret_cast<__nv_bfloat162*>(&vh4);
        __nv_bfloat162* pl = reinterpret_cast<__nv_bfloat162*>(&vl4);
#pragma unroll
        for (int i = 0; i < 4; i++) { ph[i] = __hmul2(ph[i], sc2); pl[i] = __hmul2(pl[i], sc2); }
        *reinterpret_cast<uint4*>(&Qh[r * FST + c8]) = vh4;
        *reinterpret_cast<uint4*>(&Ql[r * FST + c8]) = vl4;
    }

    float m0r = -1e30f, m1r = -1e30f, l0r = 0.f, l1r = 0.f;
    float o[8][4];
#pragma unroll
    for (int j = 0; j < 8; j++)
#pragma unroll
        for (int r = 0; r < 4; r++) o[j][r] = 0.f;

    const int ktmax = 2 * qt + 1;
    for (int kt = 0; kt <= ktmax; kt++) {
        __syncthreads();
#pragma unroll
        for (int l = 0; l < 2; l++) {
            const int idx = tid + l * 256;   // 0..511
            const int r = idx >> 3;          // 0..63
            const int c8 = (idx & 7) * 8;
            const size_t base = (size_t)(b * TT + kt * 64 + r) * QKV_COLS + h * HDIM + c8;
            uint4 kh4 = *reinterpret_cast<const uint4*>(qkvh + base + DD);
            uint4 kl4 = *reinterpret_cast<const uint4*>(qkvl + base + DD);
            *reinterpret_cast<uint4*>(&Kh[r * FST + c8]) = kh4;
            *reinterpret_cast<uint4*>(&Kl[r * FST + c8]) = kl4;
            uint4 vh4 = *reinterpret_cast<const uint4*>(qkvh + base + 2 * DD);
            uint4 vl4 = *reinterpret_cast<const uint4*>(qkvl + base + 2 * DD);
            __nv_bfloat16 eh[8], el[8];
            *reinterpret_cast<uint4*>(eh) = vh4;
            *reinterpret_cast<uint4*>(el) = vl4;
#pragma unroll
            for (int i = 0; i < 8; i++) {
                Vh[(c8 + i) * FST + r] = eh[i];
                Vl[(c8 + i) * FST + r] = el[i];
            }
        }
        __syncthreads();

        // S = Q K^T (term-batched: hh, lh, hl over j-groups of 4)
        float s[8][4];
#pragma unroll
        for (int j = 0; j < 8; j++)
#pragma unroll
            for (int r = 0; r < 4; r++) s[j][r] = 0.f;

#pragma unroll
        for (int kk = 0; kk < 4; kk++) {
            uint32_t qh[4], ql[4];
            const int base = rl0 * FST + kk * 16 + 2 * q;
            qh[0] = lds32(Qh + base);      qh[1] = lds32(Qh + base + 8 * FST);
            qh[2] = lds32(Qh + base + 8);  qh[3] = lds32(Qh + base + 8 * FST + 8);
            ql[0] = lds32(Ql + base);      ql[1] = lds32(Ql + base + 8 * FST);
            ql[2] = lds32(Ql + base + 8);  ql[3] = lds32(Ql + base + 8 * FST + 8);
#pragma unroll
            for (int jh = 0; jh < 2; jh++) {
                uint32_t kh2[4][2], kl2[4][2];
#pragma unroll
                for (int j = 0; j < 4; j++) {
                    const int bb = ((jh * 4 + j) * 8 + g) * FST + kk * 16 + 2 * q;
                    kh2[j][0] = lds32(Kh + bb); kh2[j][1] = lds32(Kh + bb + 8);
                    kl2[j][0] = lds32(Kl + bb); kl2[j][1] = lds32(Kl + bb + 8);
                }
#pragma unroll
                for (int j = 0; j < 4; j++) mma_bf16(s[jh * 4 + j], qh, kh2[j]);
#pragma unroll
                for (int j = 0; j < 4; j++) mma_bf16(s[jh * 4 + j], ql, kh2[j]);
#pragma unroll
                for (int j = 0; j < 4; j++) mma_bf16(s[jh * 4 + j], qh, kl2[j]);
            }
        }

        if (kt >= 2 * qt) {   // diagonal region: elementwise causal mask
            const int coff = kt * 64 - q0;
#pragma unroll
            for (int j = 0; j < 8; j++) {
                const int c = coff + j * 8 + 2 * q;
                if (c     > rl0) s[j][0] = -1e30f;
                if (c + 1 > rl0) s[j][1] = -1e30f;
                if (c     > rl1) s[j][2] = -1e30f;
                if (c + 1 > rl1) s[j][3] = -1e30f;
            }
        }

        // online softmax
        {
            float tm = -1e30f;
#pragma unroll
            for (int j = 0; j < 8; j++) tm = fmaxf(tm, fmaxf(s[j][0], s[j][1]));
            tm = fmaxf(tm, __shfl_xor_sync(0xffffffffu, tm, 1));
            tm = fmaxf(tm, __shfl_xor_sync(0xffffffffu, tm, 2));
            const float mn = fmaxf(m0r, tm);
            const float corr = __expf(m0r - mn);
            m0r = mn;
            float rs = 0.f;
#pragma unroll
            for (int j = 0; j < 8; j++) {
                s[j][0] = __expf(s[j][0] - mn); rs += s[j][0];
                s[j][1] = __expf(s[j][1] - mn); rs += s[j][1];
            }
            rs += __shfl_xor_sync(0xffffffffu, rs, 1);
            rs += __shfl_xor_sync(0xffffffffu, rs, 2);
            l0r = l0r * corr + rs;
#pragma unroll
            for (int j = 0; j < 8; j++) { o[j][0] *= corr; o[j][1] *= corr; }
        }
        {
            float tm = -1e30f;
#pragma unroll
            for (int j = 0; j < 8; j++) tm = fmaxf(tm, fmaxf(s[j][2], s[j][3]));
            tm = fmaxf(tm, __shfl_xor_sync(0xffffffffu, tm, 1));
            tm = fmaxf(tm, __shfl_xor_sync(0xffffffffu, tm, 2));
            const float mn = fmaxf(m1r, tm);
            const float corr = __expf(m1r - mn);
            m1r = mn;
            float rs = 0.f;
#pragma unroll
            for (int j = 0; j < 8; j++) {
                s[j][2] = __expf(s[j][2] - mn); rs += s[j][2];
                s[j][3] = __expf(s[j][3] - mn); rs += s[j][3];
            }
            rs += __shfl_xor_sync(0xffffffffu, rs, 1);
            rs += __shfl_xor_sync(0xffffffffu, rs, 2);
            l1r = l1r * corr + rs;
#pragma unroll
            for (int j = 0; j < 8; j++) { o[j][2] *= corr; o[j][3] *= corr; }
        }

        // stage split P
#pragma unroll
        for (int j = 0; j < 8; j++) {
            const int col = j * 8 + 2 * q;
#pragma unroll
            for (int half = 0; half < 2; half++) {
                const int r = (half == 0) ? rl0 : rl1;
                const float v0 = s[j][half * 2 + 0];
                const float v1 = s[j][half * 2 + 1];
                __nv_bfloat16 h0 = __float2bfloat16(v0);
                __nv_bfloat16 h1 = __float2bfloat16(v1);
                __nv_bfloat16 l0v = __float2bfloat16(v0 - __bfloat162float(h0));
                __nv_bfloat16 l1v = __float2bfloat16(v1 - __bfloat162float(h1));
                __nv_bfloat162 hp; hp.x = h0; hp.y = h1;
                __nv_bfloat162 lp; lp.x = l0v; lp.y = l1v;
                *reinterpret_cast<__nv_bfloat162*>(&Ph[r * FST + col]) = hp;
                *reinterpret_cast<__nv_bfloat162*>(&Pl[r * FST + col]) = lp;
            }
        }
        __syncthreads();

        // O += P V (term-batched over j-groups of 4)
#pragma unroll
        for (int kk = 0; kk < 4; kk++) {
            uint32_t ph[4], pl[4];
            const int base = rl0 * FST + kk * 16 + 2 * q;
            ph[0] = lds32(Ph + base);      ph[1] = lds32(Ph + base + 8 * FST);
            ph[2] = lds32(Ph + base + 8);  ph[3] = lds32(Ph + base + 8 * FST + 8);
            pl[0] = lds32(Pl + base);      pl[1] = lds32(Pl + base + 8 * FST);
            pl[2] = lds32(Pl + base + 8);  pl[3] = lds32(Pl + base + 8 * FST + 8);
#pragma unroll
            for (int jh = 0; jh < 2; jh++) {
                uint32_t vh2[4][2], vl2[4][2];
#pragma unroll
                for (int j = 0; j < 4; j++) {
                    const int bb = ((jh * 4 + j) * 8 + g) * FST + kk * 16 + 2 * q;
                    vh2[j][0] = lds32(Vh + bb); vh2[j][1] = lds32(Vh + bb + 8);
                    vl2[j][0] = lds32(Vl + bb); vl2[j][1] = lds32(Vl + bb + 8);
                }
#pragma unroll
                for (int j = 0; j < 4; j++) mma_bf16(o[jh * 4 + j], ph, vh2[j]);
#pragma unroll
                for (int j = 0; j < 4; j++) mma_bf16(o[jh * 4 + j], pl, vh2[j]);
#pragma unroll
                for (int j = 0; j < 4; j++) mma_bf16(o[jh * 4 + j], ph, vl2[j]);
            }
        }
    }

    // epilogue: normalize, split, store
    const float inv0 = 1.0f / l0r;
    const float inv1 = 1.0f / l1r;
#pragma unroll
    for (int j = 0; j < 8; j++) {
        const int col = h * HDIM + j * 8 + 2 * q;
#pragma unroll
        for (int half = 0; half < 2; half++) {
            const int r = (half == 0) ? rl0 : rl1;
            const float inv = (half == 0) ? inv0 : inv1;
            const float v0 = o[j][half * 2 + 0] * inv;
            const float v1 = o[j][half * 2 + 1] * inv;
            __nv_bfloat16 h0 = __float2bfloat16(v0);
            __nv_bfloat16 h1 = __float2bfloat16(v1);
            __nv_bfloat16 l0v = __float2bfloat16(v0 - __bfloat162float(h0));
            __nv_bfloat16 l1v = __float2bfloat16(v1 - __bfloat162float(h1));
            __nv_bfloat162 hp; hp.x = h0; hp.y = h1;
            __nv_bfloat162 lp; lp.x = l0v; lp.y = l1v;
            const size_t off = (size_t)(b * TT + q0 + r) * DD + col;
            *reinterpret_cast<__nv_bfloat162*>(&Oh[off]) = hp;
            *reinterpret_cast<__nv_bfloat162*>(&Ol[off]) = lp;
        }
    }
}

// ---------------------------------------------------------------------------
extern "C" void kernel_launch(void* const* d_in, const int* in_sizes, int n_in,
                              void* d_out, int out_size)
{
    const float* x     = (const float*)d_in[0];
    const float* Wqkv  = (const float*)d_in[1];
    const float* Wproj = (const float*)d_in[2];
    const float* bproj = (const float*)d_in[3];
    float* out = (float*)d_out;

    __nv_bfloat16 *xh, *xl, *wqh, *wql, *wph, *wpl, *qkvh, *qkvl, *ah, *al;
    cudaGetSymbolAddress((void**)&xh,   g_xh);
    cudaGetSymbolAddress((void**)&xl,   g_xl);
    cudaGetSymbolAddress((void**)&wqh,  g_wqh);
    cudaGetSymbolAddress((void**)&wql,  g_wql);
    cudaGetSymbolAddress((void**)&wph,  g_wph);
    cudaGetSymbolAddress((void**)&wpl,  g_wpl);
    cudaGetSymbolAddress((void**)&qkvh, g_qkvh);
    cudaGetSymbolAddress((void**)&qkvl, g_qkvl);
    cudaGetSymbolAddress((void**)&ah,   g_ah);
    cudaGetSymbolAddress((void**)&al,   g_al);

    cudaFuncSetAttribute(gemm_sp<true, false>,
                         cudaFuncAttributeMaxDynamicSharedMemorySize, GEMM_SMEM);
    cudaFuncSetAttribute(gemm_sp<false, true>,
                         cudaFuncAttributeMaxDynamicSharedMemorySize, GEMM_SMEM);
    cudaFuncSetAttribute(flash_sp,
                         cudaFuncAttributeMaxDynamicSharedMemorySize, FLASH_SMEM);

    // splits
    split_kernel<<<(MROWS * DD / 4 + 255) / 256, 256>>>(x, xh, xl, MROWS * DD / 4);
    split_kernel<<<(QKV_COLS * DD / 4 + 255) / 256, 256>>>(Wqkv, wqh, wql, QKV_COLS * DD / 4);
    split_kernel<<<(DD * DD / 4 + 255) / 256, 256>>>(Wproj, wph, wpl, DD * DD / 4);

    // 1) QKV projection (split output for attention)
    {
        dim3 grid(QKV_COLS / 128, MROWS / 128);
        gemm_sp<true, false><<<grid, 256, GEMM_SMEM>>>(
            xh, xl, wqh, wql, nullptr, nullptr, qkvh, qkvl, MROWS, QKV_COLS, DD);
    }
    // 2) causal flash attention (128q x 64k tiles)
    {
        dim3 grid(TT / 128, BB * HH);
        flash_sp<<<grid, 256, FLASH_SMEM>>>(qkvh, qkvl, ah, al);
    }
    // 3) output projection (fp32 out, bias)
    {
        dim3 grid(DD / 128, MROWS / 128);
        gemm_sp<false, true><<<grid, 256, GEMM_SMEM>>>(
            ah, al, wph, wpl, bproj, out, nullptr, nullptr, MROWS, DD, DD);
    }
}

// round 10
// speedup vs baseline: 1.1610x; 1.1610x over previous
#include <cuda_runtime.h>
#include <cuda_bf16.h>
#include <cstdint>

// B=4, T=2048, D=1024, H=16, HD=64
#define BB 4
#define TT 2048
#define DD 1024
#define HH 16
#define HDIM 64
#define MROWS (BB * TT)          // 8192
#define QKV_COLS (3 * DD)        // 3072

// ---------------- scratch (__device__ globals; allocation-free) -------------
__device__ __nv_bfloat16 g_xh[(size_t)MROWS * DD];
__device__ __nv_bfloat16 g_xl[(size_t)MROWS * DD];
__device__ __nv_bfloat16 g_wqh[(size_t)QKV_COLS * DD];
__device__ __nv_bfloat16 g_wql[(size_t)QKV_COLS * DD];
__device__ __nv_bfloat16 g_wph[(size_t)DD * DD];
__device__ __nv_bfloat16 g_wpl[(size_t)DD * DD];
__device__ __nv_bfloat16 g_qkvh[(size_t)MROWS * QKV_COLS];
__device__ __nv_bfloat16 g_qkvl[(size_t)MROWS * QKV_COLS];
__device__ __nv_bfloat16 g_ah[(size_t)MROWS * DD];
__device__ __nv_bfloat16 g_al[(size_t)MROWS * DD];

// ---------------- helpers ---------------------------------------------------
__device__ __forceinline__ void mma_bf16(float* c, const uint32_t* a, const uint32_t* b) {
    asm volatile(
        "mma.sync.aligned.m16n8k16.row.col.f32.bf16.bf16.f32 "
        "{%0,%1,%2,%3},{%4,%5,%6,%7},{%8,%9},{%0,%1,%2,%3};"
        : "+f"(c[0]), "+f"(c[1]), "+f"(c[2]), "+f"(c[3])
        : "r"(a[0]), "r"(a[1]), "r"(a[2]), "r"(a[3]), "r"(b[0]), "r"(b[1]));
}

__device__ __forceinline__ void ldsm4(uint32_t* r, uint32_t saddr) {
    asm volatile("ldmatrix.sync.aligned.m8n8.x4.shared.b16 {%0,%1,%2,%3}, [%4];"
        : "=r"(r[0]), "=r"(r[1]), "=r"(r[2]), "=r"(r[3]) : "r"(saddr));
}

__device__ __forceinline__ void cp16(void* smem_dst, const void* gsrc) {
    uint32_t s = (uint32_t)__cvta_generic_to_shared(smem_dst);
    asm volatile("cp.async.ca.shared.global [%0], [%1], 16;" :: "r"(s), "l"(gsrc));
}
__device__ __forceinline__ void cp_commit() { asm volatile("cp.async.commit_group;"); }
template <int N> __device__ __forceinline__ void cp_wait() {
    asm volatile("cp.async.wait_group %0;" :: "n"(N));
}

// split a pair of floats into bf16x2 hi + bf16x2 lo (round-nearest both)
__device__ __forceinline__ void split2(float f0, float f1, uint32_t& h, uint32_t& l) {
    __nv_bfloat162 hh = __floats2bfloat162_rn(f0, f1);
    float r0 = f0 - __bfloat162float(hh.x);
    float r1 = f1 - __bfloat162float(hh.y);
    __nv_bfloat162 ll = __floats2bfloat162_rn(r0, r1);
    h = *reinterpret_cast<uint32_t*>(&hh);
    l = *reinterpret_cast<uint32_t*>(&ll);
}

// ---------------- split fp32 -> (hi, lo) bf16 -------------------------------
__global__ void split_kernel(const float* __restrict__ x,
                             __nv_bfloat16* __restrict__ h,
                             __nv_bfloat16* __restrict__ l, int n4)
{
    int i = blockIdx.x * blockDim.x + threadIdx.x;
    if (i >= n4) return;
    float4 v = reinterpret_cast<const float4*>(x)[i];
    float vv[4] = {v.x, v.y, v.z, v.w};
    __nv_bfloat16 hh[4], ll[4];
#pragma unroll
    for (int k = 0; k < 4; k++) {
        hh[k] = __float2bfloat16(vv[k]);
        ll[k] = __float2bfloat16(vv[k] - __bfloat162float(hh[k]));
    }
    reinterpret_cast<uint2*>(h)[i] = *reinterpret_cast<uint2*>(hh);
    reinterpret_cast<uint2*>(l)[i] = *reinterpret_cast<uint2*>(ll);
}

// ---------------- split-bf16 GEMM: C[M,N] = A @ B^T (+bias) -----------------
// 128x128 tile, BK=32, 256 thr, 8 warps (4m x 2n), warp 32x64. cp.async x2.
// Fragment loads via ldmatrix.x4 (A: per 16x16 tile; B: per n-tile pair).
#define GST 40                      // smem row stride (bf16)
#define GTILE (128 * GST)           // 5120 bf16
#define G_AH 0
#define G_AL GTILE
#define G_BH (2 * GTILE)
#define G_BL (3 * GTILE)
#define G_STAGE (4 * GTILE)         // 20480 bf16
#define GEMM_SMEM (2 * G_STAGE * 2) // 81920 bytes

template <bool SPLIT_OUT, bool HAS_BIAS>
__global__ __launch_bounds__(256, 2) void gemm_sp(
    const __nv_bfloat16* __restrict__ Ahg, const __nv_bfloat16* __restrict__ Alg,
    const __nv_bfloat16* __restrict__ Bhg, const __nv_bfloat16* __restrict__ Blg,
    const float* __restrict__ bias,
    float* __restrict__ Cf,
    __nv_bfloat16* __restrict__ Chg, __nv_bfloat16* __restrict__ Clg,
    int M, int N, int K)
{
    extern __shared__ __nv_bfloat16 sm[];
    const int tid  = threadIdx.x;
    const int lane = tid & 31;
    const int wid  = tid >> 5;
    const int g    = lane >> 2;
    const int q    = lane & 3;
    const int m0   = (wid & 3) * 32;
    const int n0   = (wid >> 2) * 64;
    const int bRow = blockIdx.y * 128;
    const int bCol = blockIdx.x * 128;

    const int lrow = tid >> 2;          // 0..63
    const int lc8  = (tid & 3) * 8;     // 0,8,16,24

    // ldmatrix per-lane address components (element units)
    const uint32_t a_row  = m0 + (lane & 15);
    const uint32_t a_koff = (lane >> 4) * 8;
    const uint32_t b_row  = n0 + (lane & 7) + ((lane >> 4) * 8);
    const uint32_t b_koff = ((lane >> 3) & 1) * 8;
    const uint32_t smem_u32 = (uint32_t)__cvta_generic_to_shared(sm);

    float c[2][8][4];
#pragma unroll
    for (int m = 0; m < 2; m++)
#pragma unroll
        for (int n = 0; n < 8; n++)
#pragma unroll
            for (int r = 0; r < 4; r++) c[m][n][r] = 0.f;

    const int NT = K / 32;

    auto issue = [&](int t, int stg) {
        const int k0 = t * 32;
        __nv_bfloat16* s = sm + stg * G_STAGE;
        const size_t aoff0 = (size_t)(bRow + lrow) * K + k0 + lc8;
        const size_t aoff1 = (size_t)(bRow + lrow + 64) * K + k0 + lc8;
        const size_t boff0 = (size_t)(bCol + lrow) * K + k0 + lc8;
        const size_t boff1 = (size_t)(bCol + lrow + 64) * K + k0 + lc8;
        cp16(s + G_AH + lrow * GST + lc8,        Ahg + aoff0);
        cp16(s + G_AH + (lrow + 64) * GST + lc8, Ahg + aoff1);
        cp16(s + G_AL + lrow * GST + lc8,        Alg + aoff0);
        cp16(s + G_AL + (lrow + 64) * GST + lc8, Alg + aoff1);
        cp16(s + G_BH + lrow * GST + lc8,        Bhg + boff0);
        cp16(s + G_BH + (lrow + 64) * GST + lc8, Bhg + boff1);
        cp16(s + G_BL + lrow * GST + lc8,        Blg + boff0);
        cp16(s + G_BL + (lrow + 64) * GST + lc8, Blg + boff1);
    };

    issue(0, 0);
    cp_commit();

    for (int t = 0; t < NT; ++t) {
        if (t + 1 < NT) { issue(t + 1, (t + 1) & 1); cp_commit(); cp_wait<1>(); }
        else            { cp_wait<0>(); }
        __syncthreads();

        const uint32_t sb = smem_u32 + ((t & 1) * G_STAGE) * 2;
#pragma unroll
        for (int kk = 0; kk < 2; kk++) {
            uint32_t ah[2][4], al[2][4];
            const uint32_t aoff = sb + (G_AH + a_row * GST + kk * 16 + a_koff) * 2;
            ldsm4(ah[0], aoff);
            ldsm4(ah[1], aoff + 16 * GST * 2);
            const uint32_t aloff = aoff + (G_AL - G_AH) * 2;
            ldsm4(al[0], aloff);
            ldsm4(al[1], aloff + 16 * GST * 2);

            uint32_t bh[8][2], bl[8][2];
#pragma unroll
            for (int p = 0; p < 4; p++) {
                uint32_t t4[4];
                const uint32_t boff = sb + (G_BH + (b_row + p * 16) * GST + kk * 16 + b_koff) * 2;
                ldsm4(t4, boff);
                bh[2 * p][0] = t4[0]; bh[2 * p][1] = t4[1];
                bh[2 * p + 1][0] = t4[2]; bh[2 * p + 1][1] = t4[3];
                ldsm4(t4, boff + (G_BL - G_BH) * 2);
                bl[2 * p][0] = t4[0]; bl[2 * p][1] = t4[1];
                bl[2 * p + 1][0] = t4[2]; bl[2 * p + 1][1] = t4[3];
            }
#pragma unroll
            for (int n = 0; n < 8; n++)
#pragma unroll
                for (int m = 0; m < 2; m++)
                    mma_bf16(c[m][n], ah[m], bh[n]);
#pragma unroll
            for (int n = 0; n < 8; n++)
#pragma unroll
                for (int m = 0; m < 2; m++)
                    mma_bf16(c[m][n], al[m], bh[n]);
#pragma unroll
            for (int n = 0; n < 8; n++)
#pragma unroll
                for (int m = 0; m < 2; m++)
                    mma_bf16(c[m][n], ah[m], bl[n]);
        }
        __syncthreads();
    }

    // epilogue
#pragma unroll
    for (int m = 0; m < 2; m++) {
#pragma unroll
        for (int n = 0; n < 8; n++) {
            const int row = bRow + m0 + m * 16 + g;
            const int col = bCol + n0 + n * 8 + 2 * q;
#pragma unroll
            for (int half = 0; half < 2; half++) {
                const int r = row + half * 8;
                float v0 = c[m][n][half * 2 + 0];
                float v1 = c[m][n][half * 2 + 1];
                if (HAS_BIAS) { v0 += bias[col]; v1 += bias[col + 1]; }
                if (SPLIT_OUT) {
                    uint32_t hp, lp;
                    split2(v0, v1, hp, lp);
                    *reinterpret_cast<uint32_t*>(&Chg[(size_t)r * N + col]) = hp;
                    *reinterpret_cast<uint32_t*>(&Clg[(size_t)r * N + col]) = lp;
                } else {
                    float2 w; w.x = v0; w.y = v1;
                    *reinterpret_cast<float2*>(&Cf[(size_t)r * N + col]) = w;
                }
            }
        }
    }
}

// ---------------- split-bf16 causal flash attention --------------------------
// 256 thr (8 warps), 128q x 64k tiles. warp w: rows 16w..16w+15.
// ldmatrix fragment loads; P kept in registers (S-frag == A-frag layout).
#define FST 72
#define FQ  (128 * FST)              // 9216 elems
#define FK  (64 * FST)               // 4608 elems
#define F_QH 0
#define F_QL FQ
#define F_KH (2 * FQ)
#define F_KL (2 * FQ + FK)
#define F_VH (2 * FQ + 2 * FK)
#define F_VL (2 * FQ + 3 * FK)
#define FLASH_SMEM ((2 * FQ + 4 * FK) * 2)   // 73728 bytes

__global__ __launch_bounds__(256, 2) void flash_sp(
    const __nv_bfloat16* __restrict__ qkvh,
    const __nv_bfloat16* __restrict__ qkvl,
    __nv_bfloat16* __restrict__ Oh, __nv_bfloat16* __restrict__ Ol)
{
    extern __shared__ __nv_bfloat16 fsm[];
    __nv_bfloat16* Qh = fsm + F_QH;  __nv_bfloat16* Ql = fsm + F_QL;
    __nv_bfloat16* Kh = fsm + F_KH;  __nv_bfloat16* Kl = fsm + F_KL;
    __nv_bfloat16* Vh = fsm + F_VH;  __nv_bfloat16* Vl = fsm + F_VL;

    const int tid  = threadIdx.x;
    const int lane = tid & 31;
    const int wid  = tid >> 5;
    const int g    = lane >> 2;
    const int q    = lane & 3;
    const int qt   = blockIdx.x;         // 128-query tile (0..15)
    const int b    = blockIdx.y >> 4;
    const int h    = blockIdx.y & 15;
    const int q0   = qt * 128;
    const int rl0  = wid * 16 + g;       // 0..127
    const int rl1  = rl0 + 8;

    // ldmatrix per-lane address components (element units)
    const uint32_t qa_row  = wid * 16 + (lane & 15);
    const uint32_t qa_koff = (lane >> 4) * 8;
    const uint32_t kb_row  = (lane & 7) + ((lane >> 4) * 8);
    const uint32_t kb_koff = ((lane >> 3) & 1) * 8;
    const uint32_t fq_h = (uint32_t)__cvta_generic_to_shared(Qh);
    const uint32_t fq_l = (uint32_t)__cvta_generic_to_shared(Ql);
    const uint32_t fk_h = (uint32_t)__cvta_generic_to_shared(Kh);
    const uint32_t fk_l = (uint32_t)__cvta_generic_to_shared(Kl);
    const uint32_t fv_h = (uint32_t)__cvta_generic_to_shared(Vh);
    const uint32_t fv_l = (uint32_t)__cvta_generic_to_shared(Vl);

    // load Q (scaled by 1/8, exact power of two)
    __nv_bfloat162 sc2; sc2.x = __float2bfloat16(0.125f); sc2.y = sc2.x;
#pragma unroll
    for (int l = 0; l < 4; l++) {
        const int idx = tid + l * 256;   // 0..1023
        const int r = idx >> 3;          // 0..127
        const int c8 = (idx & 7) * 8;
        const size_t off = (size_t)(b * TT + q0 + r) * QKV_COLS + h * HDIM + c8;
        uint4 vh4 = *reinterpret_cast<const uint4*>(qkvh + off);
        uint4 vl4 = *reinterpret_cast<const uint4*>(qkvl + off);
        __nv_bfloat162* ph = reinterpret_cast<__nv_bfloat162*>(&vh4);
        __nv_bfloat162* pl = reinterpret_cast<__nv_bfloat162*>(&vl4);
#pragma unroll
        for (int i = 0; i < 4; i++) { ph[i] = __hmul2(ph[i], sc2); pl[i] = __hmul2(pl[i], sc2); }
        *reinterpret_cast<uint4*>(&Qh[r * FST + c8]) = vh4;
        *reinterpret_cast<uint4*>(&Ql[r * FST + c8]) = vl4;
    }

    float m0r = -1e30f, m1r = -1e30f, l0r = 0.f, l1r = 0.f;
    float o[8][4];
#pragma unroll
    for (int j = 0; j < 8; j++)
#pragma unroll
        for (int r = 0; r < 4; r++) o[j][r] = 0.f;

    const int ktmax = 2 * qt + 1;
    for (int kt = 0; kt <= ktmax; kt++) {
        __syncthreads();
#pragma unroll
        for (int l = 0; l < 2; l++) {
            const int idx = tid + l * 256;   // 0..511
            const int r = idx >> 3;          // 0..63
            const int c8 = (idx & 7) * 8;
            const size_t base = (size_t)(b * TT + kt * 64 + r) * QKV_COLS + h * HDIM + c8;
            uint4 kh4 = *reinterpret_cast<const uint4*>(qkvh + base + DD);
            uint4 kl4 = *reinterpret_cast<const uint4*>(qkvl + base + DD);
            *reinterpret_cast<uint4*>(&Kh[r * FST + c8]) = kh4;
            *reinterpret_cast<uint4*>(&Kl[r * FST + c8]) = kl4;
            uint4 vh4 = *reinterpret_cast<const uint4*>(qkvh + base + 2 * DD);
            uint4 vl4 = *reinterpret_cast<const uint4*>(qkvl + base + 2 * DD);
            __nv_bfloat16 eh[8], el[8];
            *reinterpret_cast<uint4*>(eh) = vh4;
            *reinterpret_cast<uint4*>(el) = vl4;
#pragma unroll
            for (int i = 0; i < 8; i++) {
                Vh[(c8 + i) * FST + r] = eh[i];
                Vl[(c8 + i) * FST + r] = el[i];
            }
        }
        __syncthreads();

        // S = Q K^T (hh + lh + hl) via ldmatrix
        float s[8][4];
#pragma unroll
        for (int j = 0; j < 8; j++)
#pragma unroll
            for (int r = 0; r < 4; r++) s[j][r] = 0.f;

#pragma unroll
        for (int kk = 0; kk < 4; kk++) {
            uint32_t qh[4], ql[4];
            const uint32_t qoff = (qa_row * FST + kk * 16 + qa_koff) * 2;
            ldsm4(qh, fq_h + qoff);
            ldsm4(ql, fq_l + qoff);
            uint32_t kh2[8][2], kl2[8][2];
#pragma unroll
            for (int p = 0; p < 4; p++) {
                uint32_t t4[4];
                const uint32_t koff = ((kb_row + p * 16) * FST + kk * 16 + kb_koff) * 2;
                ldsm4(t4, fk_h + koff);
                kh2[2 * p][0] = t4[0]; kh2[2 * p][1] = t4[1];
                kh2[2 * p + 1][0] = t4[2]; kh2[2 * p + 1][1] = t4[3];
                ldsm4(t4, fk_l + koff);
                kl2[2 * p][0] = t4[0]; kl2[2 * p][1] = t4[1];
                kl2[2 * p + 1][0] = t4[2]; kl2[2 * p + 1][1] = t4[3];
            }
#pragma unroll
            for (int j = 0; j < 8; j++) mma_bf16(s[j], qh, kh2[j]);
#pragma unroll
            for (int j = 0; j < 8; j++) mma_bf16(s[j], ql, kh2[j]);
#pragma unroll
            for (int j = 0; j < 8; j++) mma_bf16(s[j], qh, kl2[j]);
        }

        if (kt >= 2 * qt) {   // diagonal region: elementwise causal mask
            const int coff = kt * 64 - q0;
#pragma unroll
            for (int j = 0; j < 8; j++) {
                const int c = coff + j * 8 + 2 * q;
                if (c     > rl0) s[j][0] = -1e30f;
                if (c + 1 > rl0) s[j][1] = -1e30f;
                if (c     > rl1) s[j][2] = -1e30f;
                if (c + 1 > rl1) s[j][3] = -1e30f;
            }
        }

        // online softmax
        {
            float tm = -1e30f;
#pragma unroll
            for (int j = 0; j < 8; j++) tm = fmaxf(tm, fmaxf(s[j][0], s[j][1]));
            tm = fmaxf(tm, __shfl_xor_sync(0xffffffffu, tm, 1));
            tm = fmaxf(tm, __shfl_xor_sync(0xffffffffu, tm, 2));
            const float mn = fmaxf(m0r, tm);
            const float corr = __expf(m0r - mn);
            m0r = mn;
            float rs = 0.f;
#pragma unroll
            for (int j = 0; j < 8; j++) {
                s[j][0] = __expf(s[j][0] - mn); rs += s[j][0];
                s[j][1] = __expf(s[j][1] - mn); rs += s[j][1];
            }
            rs += __shfl_xor_sync(0xffffffffu, rs, 1);
            rs += __shfl_xor_sync(0xffffffffu, rs, 2);
            l0r = l0r * corr + rs;
#pragma unroll
            for (int j = 0; j < 8; j++) { o[j][0] *= corr; o[j][1] *= corr; }
        }
        {
            float tm = -1e30f;
#pragma unroll
            for (int j = 0; j < 8; j++) tm = fmaxf(tm, fmaxf(s[j][2], s[j][3]));
            tm = fmaxf(tm, __shfl_xor_sync(0xffffffffu, tm, 1));
            tm = fmaxf(tm, __shfl_xor_sync(0xffffffffu, tm, 2));
            const float mn = fmaxf(m1r, tm);
            const float corr = __expf(m1r - mn);
            m1r = mn;
            float rs = 0.f;
#pragma unroll
            for (int j = 0; j < 8; j++) {
                s[j][2] = __expf(s[j][2] - mn); rs += s[j][2];
                s[j][3] = __expf(s[j][3] - mn); rs += s[j][3];
            }
            rs += __shfl_xor_sync(0xffffffffu, rs, 1);
            rs += __shfl_xor_sync(0xffffffffu, rs, 2);
            l1r = l1r * corr + rs;
#pragma unroll
            for (int j = 0; j < 8; j++) { o[j][2] *= corr; o[j][3] *= corr; }
        }

        // O += P V with P split in registers (S C-frag == A-frag layout)
#pragma unroll
        for (int kk = 0; kk < 4; kk++) {
            uint32_t pa_h[4], pa_l[4];
            split2(s[2 * kk][0],     s[2 * kk][1],     pa_h[0], pa_l[0]);
            split2(s[2 * kk][2],     s[2 * kk][3],     pa_h[1], pa_l[1]);
            split2(s[2 * kk + 1][0], s[2 * kk + 1][1], pa_h[2], pa_l[2]);
            split2(s[2 * kk + 1][2], s[2 * kk + 1][3], pa_h[3], pa_l[3]);

            uint32_t vh2[8][2], vl2[8][2];
#pragma unroll
            for (int p = 0; p < 4; p++) {
                uint32_t t4[4];
                const uint32_t voff = ((kb_row + p * 16) * FST + kk * 16 + kb_koff) * 2;
                ldsm4(t4, fv_h + voff);
                vh2[2 * p][0] = t4[0]; vh2[2 * p][1] = t4[1];
                vh2[2 * p + 1][0] = t4[2]; vh2[2 * p + 1][1] = t4[3];
                ldsm4(t4, fv_l + voff);
                vl2[2 * p][0] = t4[0]; vl2[2 * p][1] = t4[1];
                vl2[2 * p + 1][0] = t4[2]; vl2[2 * p + 1][1] = t4[3];
            }
#pragma unroll
            for (int j = 0; j < 8; j++) mma_bf16(o[j], pa_h, vh2[j]);
#pragma unroll
            for (int j = 0; j < 8; j++) mma_bf16(o[j], pa_l, vh2[j]);
#pragma unroll
            for (int j = 0; j < 8; j++) mma_bf16(o[j], pa_h, vl2[j]);
        }
    }

    // epilogue: normalize, split, store
    const float inv0 = 1.0f / l0r;
    const float inv1 = 1.0f / l1r;
#pragma unroll
    for (int j = 0; j < 8; j++) {
        const int col = h * HDIM + j * 8 + 2 * q;
#pragma unroll
        for (int half = 0; half < 2; half++) {
            const int r = (half == 0) ? rl0 : rl1;
            const float inv = (half == 0) ? inv0 : inv1;
            const float v0 = o[j][half * 2 + 0] * inv;
            const float v1 = o[j][half * 2 + 1] * inv;
            uint32_t hp, lp;
            split2(v0, v1, hp, lp);
            const size_t off = (size_t)(b * TT + q0 + r) * DD + col;
            *reinterpret_cast<uint32_t*>(&Oh[off]) = hp;
            *reinterpret_cast<uint32_t*>(&Ol[off]) = lp;
        }
    }
}

// ---------------------------------------------------------------------------
extern "C" void kernel_launch(void* const* d_in, const int* in_sizes, int n_in,
                              void* d_out, int out_size)
{
    const float* x     = (const float*)d_in[0];
    const float* Wqkv  = (const float*)d_in[1];
    const float* Wproj = (const float*)d_in[2];
    const float* bproj = (const float*)d_in[3];
    float* out = (float*)d_out;

    __nv_bfloat16 *xh, *xl, *wqh, *wql, *wph, *wpl, *qkvh, *qkvl, *ah, *al;
    cudaGetSymbolAddress((void**)&xh,   g_xh);
    cudaGetSymbolAddress((void**)&xl,   g_xl);
    cudaGetSymbolAddress((void**)&wqh,  g_wqh);
    cudaGetSymbolAddress((void**)&wql,  g_wql);
    cudaGetSymbolAddress((void**)&wph,  g_wph);
    cudaGetSymbolAddress((void**)&wpl,  g_wpl);
    cudaGetSymbolAddress((void**)&qkvh, g_qkvh);
    cudaGetSymbolAddress((void**)&qkvl, g_qkvl);
    cudaGetSymbolAddress((void**)&ah,   g_ah);
    cudaGetSymbolAddress((void**)&al,   g_al);

    cudaFuncSetAttribute(gemm_sp<true, false>,
                         cudaFuncAttributeMaxDynamicSharedMemorySize, GEMM_SMEM);
    cudaFuncSetAttribute(gemm_sp<false, true>,
                         cudaFuncAttributeMaxDynamicSharedMemorySize, GEMM_SMEM);
    cudaFuncSetAttribute(flash_sp,
                         cudaFuncAttributeMaxDynamicSharedMemorySize, FLASH_SMEM);

    // splits
    split_kernel<<<(MROWS * DD / 4 + 255) / 256, 256>>>(x, xh, xl, MROWS * DD / 4);
    split_kernel<<<(QKV_COLS * DD / 4 + 255) / 256, 256>>>(Wqkv, wqh, wql, QKV_COLS * DD / 4);
    split_kernel<<<(DD * DD / 4 + 255) / 256, 256>>>(Wproj, wph, wpl, DD * DD / 4);

    // 1) QKV projection (split output for attention)
    {
        dim3 grid(QKV_COLS / 128, MROWS / 128);
        gemm_sp<true, false><<<grid, 256, GEMM_SMEM>>>(
            xh, xl, wqh, wql, nullptr, nullptr, qkvh, qkvl, MROWS, QKV_COLS, DD);
    }
    // 2) causal flash attention (128q x 64k tiles)
    {
        dim3 grid(TT / 128, BB * HH);
        flash_sp<<<grid, 256, FLASH_SMEM>>>(qkvh, qkvl, ah, al);
    }
    // 3) output projection (fp32 out, bias)
    {
        dim3 grid(DD / 128, MROWS / 128);
        gemm_sp<false, true><<<grid, 256, GEMM_SMEM>>>(
            ah, al, wph, wpl, bproj, out, nullptr, nullptr, MROWS, DD, DD);
    }
}

// round 13
// speedup vs baseline: 1.2980x; 1.1180x over previous
#include <cuda_runtime.h>
#include <cuda_bf16.h>
#include <cstdint>

// B=4, T=2048, D=1024, H=16, HD=64
#define BB 4
#define TT 2048
#define DD 1024
#define HH 16
#define HDIM 64
#define MROWS (BB * TT)          // 8192
#define QKV_COLS (3 * DD)        // 3072

// ---------------- scratch (__device__ globals; allocation-free) -------------
__device__ __nv_bfloat16 g_xh[(size_t)MROWS * DD];
__device__ __nv_bfloat16 g_xl[(size_t)MROWS * DD];
__device__ __nv_bfloat16 g_wqh[(size_t)QKV_COLS * DD];
__device__ __nv_bfloat16 g_wql[(size_t)QKV_COLS * DD];
__device__ __nv_bfloat16 g_wph[(size_t)DD * DD];
__device__ __nv_bfloat16 g_wpl[(size_t)DD * DD];
__device__ __nv_bfloat16 g_qkvh[(size_t)MROWS * QKV_COLS];
__device__ __nv_bfloat16 g_qkvl[(size_t)MROWS * QKV_COLS];
__device__ __nv_bfloat16 g_ah[(size_t)MROWS * DD];
__device__ __nv_bfloat16 g_al[(size_t)MROWS * DD];

// ---------------- helpers ---------------------------------------------------
__device__ __forceinline__ void mma_bf16(float* c, const uint32_t* a, const uint32_t* b) {
    asm volatile(
        "mma.sync.aligned.m16n8k16.row.col.f32.bf16.bf16.f32 "
        "{%0,%1,%2,%3},{%4,%5,%6,%7},{%8,%9},{%0,%1,%2,%3};"
        : "+f"(c[0]), "+f"(c[1]), "+f"(c[2]), "+f"(c[3])
        : "r"(a[0]), "r"(a[1]), "r"(a[2]), "r"(a[3]), "r"(b[0]), "r"(b[1]));
}

__device__ __forceinline__ void ldsm4(uint32_t* r, uint32_t saddr) {
    asm volatile("ldmatrix.sync.aligned.m8n8.x4.shared.b16 {%0,%1,%2,%3}, [%4];"
        : "=r"(r[0]), "=r"(r[1]), "=r"(r[2]), "=r"(r[3]) : "r"(saddr));
}
__device__ __forceinline__ void ldsm4t(uint32_t* r, uint32_t saddr) {
    asm volatile("ldmatrix.sync.aligned.m8n8.x4.trans.shared.b16 {%0,%1,%2,%3}, [%4];"
        : "=r"(r[0]), "=r"(r[1]), "=r"(r[2]), "=r"(r[3]) : "r"(saddr));
}

__device__ __forceinline__ void cp16(void* smem_dst, const void* gsrc) {
    uint32_t s = (uint32_t)__cvta_generic_to_shared(smem_dst);
    asm volatile("cp.async.ca.shared.global [%0], [%1], 16;" :: "r"(s), "l"(gsrc));
}
__device__ __forceinline__ void cp_commit() { asm volatile("cp.async.commit_group;"); }
template <int N> __device__ __forceinline__ void cp_wait() {
    asm volatile("cp.async.wait_group %0;" :: "n"(N));
}

// split a pair of floats into bf16x2 hi + bf16x2 lo (round-nearest both)
__device__ __forceinline__ void split2(float f0, float f1, uint32_t& h, uint32_t& l) {
    __nv_bfloat162 hh = __floats2bfloat162_rn(f0, f1);
    float r0 = f0 - __bfloat162float(hh.x);
    float r1 = f1 - __bfloat162float(hh.y);
    __nv_bfloat162 ll = __floats2bfloat162_rn(r0, r1);
    h = *reinterpret_cast<uint32_t*>(&hh);
    l = *reinterpret_cast<uint32_t*>(&ll);
}

// ---------------- split fp32 -> (hi, lo) bf16 -------------------------------
__global__ void split_kernel(const float* __restrict__ x,
                             __nv_bfloat16* __restrict__ h,
                             __nv_bfloat16* __restrict__ l, int n4)
{
    int i = blockIdx.x * blockDim.x + threadIdx.x;
    if (i >= n4) return;
    float4 v = reinterpret_cast<const float4*>(x)[i];
    float vv[4] = {v.x, v.y, v.z, v.w};
    __nv_bfloat16 hh[4], ll[4];
#pragma unroll
    for (int k = 0; k < 4; k++) {
        hh[k] = __float2bfloat16(vv[k]);
        ll[k] = __float2bfloat16(vv[k] - __bfloat162float(hh[k]));
    }
    reinterpret_cast<uint2*>(h)[i] = *reinterpret_cast<uint2*>(hh);
    reinterpret_cast<uint2*>(l)[i] = *reinterpret_cast<uint2*>(ll);
}

// ---------------- split-bf16 GEMM: C[M,N] = A @ B^T (+bias) -----------------
// (unchanged from R10 — 128x128, BK=32, ldmatrix, 2 CTAs/SM)
#define GST 40
#define GTILE (128 * GST)
#define G_AH 0
#define G_AL GTILE
#define G_BH (2 * GTILE)
#define G_BL (3 * GTILE)
#define G_STAGE (4 * GTILE)
#define GEMM_SMEM (2 * G_STAGE * 2)

template <bool SPLIT_OUT, bool HAS_BIAS>
__global__ __launch_bounds__(256, 2) void gemm_sp(
    const __nv_bfloat16* __restrict__ Ahg, const __nv_bfloat16* __restrict__ Alg,
    const __nv_bfloat16* __restrict__ Bhg, const __nv_bfloat16* __restrict__ Blg,
    const float* __restrict__ bias,
    float* __restrict__ Cf,
    __nv_bfloat16* __restrict__ Chg, __nv_bfloat16* __restrict__ Clg,
    int M, int N, int K)
{
    extern __shared__ __nv_bfloat16 sm[];
    const int tid  = threadIdx.x;
    const int lane = tid & 31;
    const int wid  = tid >> 5;
    const int g    = lane >> 2;
    const int q    = lane & 3;
    const int m0   = (wid & 3) * 32;
    const int n0   = (wid >> 2) * 64;
    const int bRow = blockIdx.y * 128;
    const int bCol = blockIdx.x * 128;

    const int lrow = tid >> 2;
    const int lc8  = (tid & 3) * 8;

    const uint32_t a_row  = m0 + (lane & 15);
    const uint32_t a_koff = (lane >> 4) * 8;
    const uint32_t b_row  = n0 + (lane & 7) + ((lane >> 4) * 8);
    const uint32_t b_koff = ((lane >> 3) & 1) * 8;
    const uint32_t smem_u32 = (uint32_t)__cvta_generic_to_shared(sm);

    float c[2][8][4];
#pragma unroll
    for (int m = 0; m < 2; m++)
#pragma unroll
        for (int n = 0; n < 8; n++)
#pragma unroll
            for (int r = 0; r < 4; r++) c[m][n][r] = 0.f;

    const int NT = K / 32;

    auto issue = [&](int t, int stg) {
        const int k0 = t * 32;
        __nv_bfloat16* s = sm + stg * G_STAGE;
        const size_t aoff0 = (size_t)(bRow + lrow) * K + k0 + lc8;
        const size_t aoff1 = (size_t)(bRow + lrow + 64) * K + k0 + lc8;
        const size_t boff0 = (size_t)(bCol + lrow) * K + k0 + lc8;
        const size_t boff1 = (size_t)(bCol + lrow + 64) * K + k0 + lc8;
        cp16(s + G_AH + lrow * GST + lc8,        Ahg + aoff0);
        cp16(s + G_AH + (lrow + 64) * GST + lc8, Ahg + aoff1);
        cp16(s + G_AL + lrow * GST + lc8,        Alg + aoff0);
        cp16(s + G_AL + (lrow + 64) * GST + lc8, Alg + aoff1);
        cp16(s + G_BH + lrow * GST + lc8,        Bhg + boff0);
        cp16(s + G_BH + (lrow + 64) * GST + lc8, Bhg + boff1);
        cp16(s + G_BL + lrow * GST + lc8,        Blg + boff0);
        cp16(s + G_BL + (lrow + 64) * GST + lc8, Blg + boff1);
    };

    issue(0, 0);
    cp_commit();

    for (int t = 0; t < NT; ++t) {
        if (t + 1 < NT) { issue(t + 1, (t + 1) & 1); cp_commit(); cp_wait<1>(); }
        else            { cp_wait<0>(); }
        __syncthreads();

        const uint32_t sb = smem_u32 + ((t & 1) * G_STAGE) * 2;
#pragma unroll
        for (int kk = 0; kk < 2; kk++) {
            uint32_t ah[2][4], al[2][4];
            const uint32_t aoff = sb + (G_AH + a_row * GST + kk * 16 + a_koff) * 2;
            ldsm4(ah[0], aoff);
            ldsm4(ah[1], aoff + 16 * GST * 2);
            const uint32_t aloff = aoff + (G_AL - G_AH) * 2;
            ldsm4(al[0], aloff);
            ldsm4(al[1], aloff + 16 * GST * 2);

            uint32_t bh[8][2], bl[8][2];
#pragma unroll
            for (int p = 0; p < 4; p++) {
                uint32_t t4[4];
                const uint32_t boff = sb + (G_BH + (b_row + p * 16) * GST + kk * 16 + b_koff) * 2;
                ldsm4(t4, boff);
                bh[2 * p][0] = t4[0]; bh[2 * p][1] = t4[1];
                bh[2 * p + 1][0] = t4[2]; bh[2 * p + 1][1] = t4[3];
                ldsm4(t4, boff + (G_BL - G_BH) * 2);
                bl[2 * p][0] = t4[0]; bl[2 * p][1] = t4[1];
                bl[2 * p + 1][0] = t4[2]; bl[2 * p + 1][1] = t4[3];
            }
#pragma unroll
            for (int n = 0; n < 8; n++)
#pragma unroll
                for (int m = 0; m < 2; m++)
                    mma_bf16(c[m][n], ah[m], bh[n]);
#pragma unroll
            for (int n = 0; n < 8; n++)
#pragma unroll
                for (int m = 0; m < 2; m++)
                    mma_bf16(c[m][n], al[m], bh[n]);
#pragma unroll
            for (int n = 0; n < 8; n++)
#pragma unroll
                for (int m = 0; m < 2; m++)
                    mma_bf16(c[m][n], ah[m], bl[n]);
        }
        __syncthreads();
    }

    // epilogue
#pragma unroll
    for (int m = 0; m < 2; m++) {
#pragma unroll
        for (int n = 0; n < 8; n++) {
            const int row = bRow + m0 + m * 16 + g;
            const int col = bCol + n0 + n * 8 + 2 * q;
#pragma unroll
            for (int half = 0; half < 2; half++) {
                const int r = row + half * 8;
                float v0 = c[m][n][half * 2 + 0];
                float v1 = c[m][n][half * 2 + 1];
                if (HAS_BIAS) { v0 += bias[col]; v1 += bias[col + 1]; }
                if (SPLIT_OUT) {
                    uint32_t hp, lp;
                    split2(v0, v1, hp, lp);
                    *reinterpret_cast<uint32_t*>(&Chg[(size_t)r * N + col]) = hp;
                    *reinterpret_cast<uint32_t*>(&Clg[(size_t)r * N + col]) = lp;
                } else {
                    float2 w; w.x = v0; w.y = v1;
                    *reinterpret_cast<float2*>(&Cf[(size_t)r * N + col]) = w;
                }
            }
        }
    }
}

// ---------------- split-bf16 causal flash attention --------------------------
// 256 thr (8 warps), 128q x 64k tiles. cp.async K/V double-buffer; V row-major
// + ldmatrix.trans; scale folded into exp; P split in registers.
#define FST 72
#define FQ_E  (128 * FST)            // 9216 elems per Q array
#define FKV_E (64 * FST)             // 4608 elems per K/V array
// element offsets within fsm
#define E_QH 0
#define E_QL FQ_E
#define E_KV(stage) (2 * FQ_E + (stage) * 4 * FKV_E)
#define E_KH 0
#define E_KL FKV_E
#define E_VH (2 * FKV_E)
#define E_VL (3 * FKV_E)
#define FLASH_SMEM ((2 * FQ_E + 8 * FKV_E) * 2)   // 110592 bytes

__global__ __launch_bounds__(256, 2) void flash_sp(
    const __nv_bfloat16* __restrict__ qkvh,
    const __nv_bfloat16* __restrict__ qkvl,
    __nv_bfloat16* __restrict__ Oh, __nv_bfloat16* __restrict__ Ol)
{
    extern __shared__ __nv_bfloat16 fsm[];

    const int tid  = threadIdx.x;
    const int lane = tid & 31;
    const int wid  = tid >> 5;
    const int g    = lane >> 2;
    const int q    = lane & 3;
    const int qt   = blockIdx.x;         // 128-query tile (0..15)
    const int b    = blockIdx.y >> 4;
    const int h    = blockIdx.y & 15;
    const int q0   = qt * 128;
    const int rl0  = wid * 16 + g;       // 0..127
    const int rl1  = rl0 + 8;

    // ldmatrix per-lane address components (element units)
    const uint32_t qa_row  = wid * 16 + (lane & 15);
    const uint32_t qa_koff = (lane >> 4) * 8;
    const uint32_t kb_row  = (lane & 7) + ((lane >> 4) * 8);   // K: rows over n
    const uint32_t kb_koff = ((lane >> 3) & 1) * 8;
    const uint32_t vt_row  = (lane & 7) + (((lane >> 3) & 1) * 8);  // V trans: rows over k
    const uint32_t vt_col  = (lane >> 4) * 8;
    const uint32_t fbase = (uint32_t)__cvta_generic_to_shared(fsm);

    // ---- async loaders ----
    auto issue_q = [&]() {
#pragma unroll
        for (int l = 0; l < 4; l++) {
            const int idx = tid + l * 256;   // 0..1023
            const int r = idx >> 3;          // 0..127
            const int c8 = (idx & 7) * 8;
            const size_t off = (size_t)(b * TT + q0 + r) * QKV_COLS + h * HDIM + c8;
            cp16(fsm + E_QH + r * FST + c8, qkvh + off);
            cp16(fsm + E_QL + r * FST + c8, qkvl + off);
        }
    };
    auto issue_kv = [&](int kt, int stage) {
        __nv_bfloat16* s = fsm + E_KV(stage);
#pragma unroll
        for (int l = 0; l < 2; l++) {
            const int idx = tid + l * 256;   // 0..511
            const int r = idx >> 3;          // 0..63
            const int c8 = (idx & 7) * 8;
            const size_t base = (size_t)(b * TT + kt * 64 + r) * QKV_COLS + h * HDIM + c8;
            cp16(s + E_KH + r * FST + c8, qkvh + base + DD);
            cp16(s + E_KL + r * FST + c8, qkvl + base + DD);
            cp16(s + E_VH + r * FST + c8, qkvh + base + 2 * DD);
            cp16(s + E_VL + r * FST + c8, qkvl + base + 2 * DD);
        }
    };

    const int ktmax = 2 * qt + 1;        // >= 1 always

    issue_q();
    issue_kv(0, 0);
    cp_commit();
    issue_kv(1, 1);
    cp_commit();

    float m0r = -1e30f, m1r = -1e30f, l0r = 0.f, l1r = 0.f;
    float o[8][4];
#pragma unroll
    for (int j = 0; j < 8; j++)
#pragma unroll
        for (int r = 0; r < 4; r++) o[j][r] = 0.f;

    for (int kt = 0; kt <= ktmax; kt++) {
        if (kt < ktmax) cp_wait<1>(); else cp_wait<0>();
        __syncthreads();

        const int stage = kt & 1;
        const uint32_t kvb = fbase + E_KV(stage) * 2;
        const uint32_t kh_b = kvb;
        const uint32_t vh_b = kvb + E_VH * 2;

        // S = Q K^T (hh + lh + hl) via ldmatrix
        float s[8][4];
#pragma unroll
        for (int j = 0; j < 8; j++)
#pragma unroll
            for (int r = 0; r < 4; r++) s[j][r] = 0.f;

#pragma unroll
        for (int kk = 0; kk < 4; kk++) {
            uint32_t qh[4], ql[4];
            const uint32_t qoff = fbase + (qa_row * FST + kk * 16 + qa_koff) * 2;
            ldsm4(qh, qoff);
            ldsm4(ql, qoff + FQ_E * 2);
            uint32_t kh2[8][2], kl2[8][2];
#pragma unroll
            for (int p = 0; p < 4; p++) {
                uint32_t t4[4];
                const uint32_t koff = kh_b + ((kb_row + p * 16) * FST + kk * 16 + kb_koff) * 2;
                ldsm4(t4, koff);
                kh2[2 * p][0] = t4[0]; kh2[2 * p][1] = t4[1];
                kh2[2 * p + 1][0] = t4[2]; kh2[2 * p + 1][1] = t4[3];
                ldsm4(t4, koff + FKV_E * 2);
                kl2[2 * p][0] = t4[0]; kl2[2 * p][1] = t4[1];
                kl2[2 * p + 1][0] = t4[2]; kl2[2 * p + 1][1] = t4[3];
            }
#pragma unroll
            for (int j = 0; j < 8; j++) mma_bf16(s[j], qh, kh2[j]);
#pragma unroll
            for (int j = 0; j < 8; j++) mma_bf16(s[j], ql, kh2[j]);
#pragma unroll
            for (int j = 0; j < 8; j++) mma_bf16(s[j], qh, kl2[j]);
        }

        if (kt >= 2 * qt) {   // diagonal region: elementwise causal mask
            const int coff = kt * 64 - q0;
#pragma unroll
            for (int j = 0; j < 8; j++) {
                const int c = coff + j * 8 + 2 * q;
                if (c     > rl0) s[j][0] = -1e30f;
                if (c + 1 > rl0) s[j][1] = -1e30f;
                if (c     > rl1) s[j][2] = -1e30f;
                if (c + 1 > rl1) s[j][3] = -1e30f;
            }
        }

        // online softmax (scale 1/8 folded into exp args; exact pow2)
        {
            float tm = -1e30f;
#pragma unroll
            for (int j = 0; j < 8; j++) tm = fmaxf(tm, fmaxf(s[j][0], s[j][1]));
            tm = fmaxf(tm, __shfl_xor_sync(0xffffffffu, tm, 1));
            tm = fmaxf(tm, __shfl_xor_sync(0xffffffffu, tm, 2));
            const float mn = fmaxf(m0r, tm);
            const float corr = __expf((m0r - mn) * 0.125f);
            m0r = mn;
            float rs = 0.f;
#pragma unroll
            for (int j = 0; j < 8; j++) {
                s[j][0] = __expf((s[j][0] - mn) * 0.125f); rs += s[j][0];
                s[j][1] = __expf((s[j][1] - mn) * 0.125f); rs += s[j][1];
            }
            rs += __shfl_xor_sync(0xffffffffu, rs, 1);
            rs += __shfl_xor_sync(0xffffffffu, rs, 2);
            l0r = l0r * corr + rs;
#pragma unroll
            for (int j = 0; j < 8; j++) { o[j][0] *= corr; o[j][1] *= corr; }
        }
        {
            float tm = -1e30f;
#pragma unroll
            for (int j = 0; j < 8; j++) tm = fmaxf(tm, fmaxf(s[j][2], s[j][3]));
            tm = fmaxf(tm, __shfl_xor_sync(0xffffffffu, tm, 1));
            tm = fmaxf(tm, __shfl_xor_sync(0xffffffffu, tm, 2));
            const float mn = fmaxf(m1r, tm);
            const float corr = __expf((m1r - mn) * 0.125f);
            m1r = mn;
            float rs = 0.f;
#pragma unroll
            for (int j = 0; j < 8; j++) {
                s[j][2] = __expf((s[j][2] - mn) * 0.125f); rs += s[j][2];
                s[j][3] = __expf((s[j][3] - mn) * 0.125f); rs += s[j][3];
            }
            rs += __shfl_xor_sync(0xffffffffu, rs, 1);
            rs += __shfl_xor_sync(0xffffffffu, rs, 2);
            l1r = l1r * corr + rs;
#pragma unroll
            for (int j = 0; j < 8; j++) { o[j][2] *= corr; o[j][3] *= corr; }
        }

        // O += P V : P split in registers; V via ldmatrix.trans (row-major smem)
#pragma unroll
        for (int kk = 0; kk < 4; kk++) {
            uint32_t pa_h[4], pa_l[4];
            split2(s[2 * kk][0],     s[2 * kk][1],     pa_h[0], pa_l[0]);
            split2(s[2 * kk][2],     s[2 * kk][3],     pa_h[1], pa_l[1]);
            split2(s[2 * kk + 1][0], s[2 * kk + 1][1], pa_h[2], pa_l[2]);
            split2(s[2 * kk + 1][2], s[2 * kk + 1][3], pa_h[3], pa_l[3]);

            uint32_t vh2[8][2], vl2[8][2];
#pragma unroll
            for (int p = 0; p < 4; p++) {
                uint32_t t4[4];
                const uint32_t voff = vh_b + ((kk * 16 + vt_row) * FST + p * 16 + vt_col) * 2;
                ldsm4t(t4, voff);
                vh2[2 * p][0] = t4[0]; vh2[2 * p][1] = t4[1];
                vh2[2 * p + 1][0] = t4[2]; vh2[2 * p + 1][1] = t4[3];
                ldsm4t(t4, voff + FKV_E * 2);
                vl2[2 * p][0] = t4[0]; vl2[2 * p][1] = t4[1];
                vl2[2 * p + 1][0] = t4[2]; vl2[2 * p + 1][1] = t4[3];
            }
#pragma unroll
            for (int j = 0; j < 8; j++) mma_bf16(o[j], pa_h, vh2[j]);
#pragma unroll
            for (int j = 0; j < 8; j++) mma_bf16(o[j], pa_l, vh2[j]);
#pragma unroll
            for (int j = 0; j < 8; j++) mma_bf16(o[j], pa_h, vl2[j]);
        }

        __syncthreads();   // all warps done with this stage before refill
        if (kt + 2 <= ktmax) {
            issue_kv(kt + 2, stage);
            cp_commit();
        }
    }

    // epilogue: normalize, split, store
    const float inv0 = 1.0f / l0r;
    const float inv1 = 1.0f / l1r;
#pragma unroll
    for (int j = 0; j < 8; j++) {
        const int col = h * HDIM + j * 8 + 2 * q;
#pragma unroll
        for (int half = 0; half < 2; half++) {
            const int r = (half == 0) ? rl0 : rl1;
            const float inv = (half == 0) ? inv0 : inv1;
            const float v0 = o[j][half * 2 + 0] * inv;
            const float v1 = o[j][half * 2 + 1] * inv;
            uint32_t hp, lp;
            split2(v0, v1, hp, lp);
            const size_t off = (size_t)(b * TT + q0 + r) * DD + col;
            *reinterpret_cast<uint32_t*>(&Oh[off]) = hp;
            *reinterpret_cast<uint32_t*>(&Ol[off]) = lp;
        }
    }
}

// ---------------------------------------------------------------------------
extern "C" void kernel_launch(void* const* d_in, const int* in_sizes, int n_in,
                              void* d_out, int out_size)
{
    const float* x     = (const float*)d_in[0];
    const float* Wqkv  = (const float*)d_in[1];
    const float* Wproj = (const float*)d_in[2];
    const float* bproj = (const float*)d_in[3];
    float* out = (float*)d_out;

    __nv_bfloat16 *xh, *xl, *wqh, *wql, *wph, *wpl, *qkvh, *qkvl, *ah, *al;
    cudaGetSymbolAddress((void**)&xh,   g_xh);
    cudaGetSymbolAddress((void**)&xl,   g_xl);
    cudaGetSymbolAddress((void**)&wqh,  g_wqh);
    cudaGetSymbolAddress((void**)&wql,  g_wql);
    cudaGetSymbolAddress((void**)&wph,  g_wph);
    cudaGetSymbolAddress((void**)&wpl,  g_wpl);
    cudaGetSymbolAddress((void**)&qkvh, g_qkvh);
    cudaGetSymbolAddress((void**)&qkvl, g_qkvl);
    cudaGetSymbolAddress((void**)&ah,   g_ah);
    cudaGetSymbolAddress((void**)&al,   g_al);

    cudaFuncSetAttribute(gemm_sp<true, false>,
                         cudaFuncAttributeMaxDynamicSharedMemorySize, GEMM_SMEM);
    cudaFuncSetAttribute(gemm_sp<false, true>,
                         cudaFuncAttributeMaxDynamicSharedMemorySize, GEMM_SMEM);
    cudaFuncSetAttribute(flash_sp,
                         cudaFuncAttributeMaxDynamicSharedMemorySize, FLASH_SMEM);

    // splits
    split_kernel<<<(MROWS * DD / 4 + 255) / 256, 256>>>(x, xh, xl, MROWS * DD / 4);
    split_kernel<<<(QKV_COLS * DD / 4 + 255) / 256, 256>>>(Wqkv, wqh, wql, QKV_COLS * DD / 4);
    split_kernel<<<(DD * DD / 4 + 255) / 256, 256>>>(Wproj, wph, wpl, DD * DD / 4);

    // 1) QKV projection (split output for attention)
    {
        dim3 grid(QKV_COLS / 128, MROWS / 128);
        gemm_sp<true, false><<<grid, 256, GEMM_SMEM>>>(
            xh, xl, wqh, wql, nullptr, nullptr, qkvh, qkvl, MROWS, QKV_COLS, DD);
    }
    // 2) causal flash attention (128q x 64k tiles)
    {
        dim3 grid(TT / 128, BB * HH);
        flash_sp<<<grid, 256, FLASH_SMEM>>>(qkvh, qkvl, ah, al);
    }
    // 3) output projection (fp32 out, bias)
    {
        dim3 grid(DD / 128, MROWS / 128);
        gemm_sp<false, true><<<grid, 256, GEMM_SMEM>>>(
            ah, al, wph, wpl, bproj, out, nullptr, nullptr, MROWS, DD, DD);
    }
}

// round 14
// speedup vs baseline: 1.3231x; 1.0194x over previous
#include <cuda_runtime.h>
#include <cuda_bf16.h>
#include <cstdint>

// B=4, T=2048, D=1024, H=16, HD=64
#define BB 4
#define TT 2048
#define DD 1024
#define HH 16
#define HDIM 64
#define MROWS (BB * TT)          // 8192
#define QKV_COLS (3 * DD)        // 3072

// ---------------- scratch (__device__ globals; allocation-free) -------------
__device__ __nv_bfloat16 g_xh[(size_t)MROWS * DD];
__device__ __nv_bfloat16 g_xl[(size_t)MROWS * DD];
__device__ __nv_bfloat16 g_wqh[(size_t)QKV_COLS * DD];
__device__ __nv_bfloat16 g_wql[(size_t)QKV_COLS * DD];
__device__ __nv_bfloat16 g_wph[(size_t)DD * DD];
__device__ __nv_bfloat16 g_wpl[(size_t)DD * DD];
__device__ __nv_bfloat16 g_qkvh[(size_t)MROWS * QKV_COLS];
__device__ __nv_bfloat16 g_qkvl[(size_t)MROWS * QKV_COLS];
__device__ __nv_bfloat16 g_ah[(size_t)MROWS * DD];
__device__ __nv_bfloat16 g_al[(size_t)MROWS * DD];

// ---------------- helpers ---------------------------------------------------
__device__ __forceinline__ void mma_bf16(float* c, const uint32_t* a, const uint32_t* b) {
    asm volatile(
        "mma.sync.aligned.m16n8k16.row.col.f32.bf16.bf16.f32 "
        "{%0,%1,%2,%3},{%4,%5,%6,%7},{%8,%9},{%0,%1,%2,%3};"
        : "+f"(c[0]), "+f"(c[1]), "+f"(c[2]), "+f"(c[3])
        : "r"(a[0]), "r"(a[1]), "r"(a[2]), "r"(a[3]), "r"(b[0]), "r"(b[1]));
}

__device__ __forceinline__ void ldsm4(uint32_t* r, uint32_t saddr) {
    asm volatile("ldmatrix.sync.aligned.m8n8.x4.shared.b16 {%0,%1,%2,%3}, [%4];"
        : "=r"(r[0]), "=r"(r[1]), "=r"(r[2]), "=r"(r[3]) : "r"(saddr));
}
__device__ __forceinline__ void ldsm4t(uint32_t* r, uint32_t saddr) {
    asm volatile("ldmatrix.sync.aligned.m8n8.x4.trans.shared.b16 {%0,%1,%2,%3}, [%4];"
        : "=r"(r[0]), "=r"(r[1]), "=r"(r[2]), "=r"(r[3]) : "r"(saddr));
}

__device__ __forceinline__ void cp16(void* smem_dst, const void* gsrc) {
    uint32_t s = (uint32_t)__cvta_generic_to_shared(smem_dst);
    asm volatile("cp.async.ca.shared.global [%0], [%1], 16;" :: "r"(s), "l"(gsrc));
}
__device__ __forceinline__ void cp_commit() { asm volatile("cp.async.commit_group;"); }
template <int N> __device__ __forceinline__ void cp_wait() {
    asm volatile("cp.async.wait_group %0;" :: "n"(N));
}

// split a pair of floats into bf16x2 hi + bf16x2 lo (round-nearest both)
__device__ __forceinline__ void split2(float f0, float f1, uint32_t& h, uint32_t& l) {
    __nv_bfloat162 hh = __floats2bfloat162_rn(f0, f1);
    float r0 = f0 - __bfloat162float(hh.x);
    float r1 = f1 - __bfloat162float(hh.y);
    __nv_bfloat162 ll = __floats2bfloat162_rn(r0, r1);
    h = *reinterpret_cast<uint32_t*>(&hh);
    l = *reinterpret_cast<uint32_t*>(&ll);
}

// ---------------- split fp32 -> (hi, lo) bf16 -------------------------------
__global__ void split_kernel(const float* __restrict__ x,
                             __nv_bfloat16* __restrict__ h,
                             __nv_bfloat16* __restrict__ l, int n4)
{
    int i = blockIdx.x * blockDim.x + threadIdx.x;
    if (i >= n4) return;
    float4 v = reinterpret_cast<const float4*>(x)[i];
    float vv[4] = {v.x, v.y, v.z, v.w};
    __nv_bfloat16 hh[4], ll[4];
#pragma unroll
    for (int k = 0; k < 4; k++) {
        hh[k] = __float2bfloat16(vv[k]);
        ll[k] = __float2bfloat16(vv[k] - __bfloat162float(hh[k]));
    }
    reinterpret_cast<uint2*>(h)[i] = *reinterpret_cast<uint2*>(hh);
    reinterpret_cast<uint2*>(l)[i] = *reinterpret_cast<uint2*>(ll);
}

// ---------------- split-bf16 GEMM: C[M,N] = A @ B^T (+bias) -----------------
// 128x128, BK=32, ldmatrix, 2 CTAs/SM. Single-barrier 2-stage pipeline:
// per iter: wait(stage t) -> sync -> issue(t+1) -> compute(t).
#define GST 40
#define GTILE (128 * GST)
#define G_AH 0
#define G_AL GTILE
#define G_BH (2 * GTILE)
#define G_BL (3 * GTILE)
#define G_STAGE (4 * GTILE)
#define GEMM_SMEM (2 * G_STAGE * 2)

template <bool SPLIT_OUT, bool HAS_BIAS>
__global__ __launch_bounds__(256, 2) void gemm_sp(
    const __nv_bfloat16* __restrict__ Ahg, const __nv_bfloat16* __restrict__ Alg,
    const __nv_bfloat16* __restrict__ Bhg, const __nv_bfloat16* __restrict__ Blg,
    const float* __restrict__ bias,
    float* __restrict__ Cf,
    __nv_bfloat16* __restrict__ Chg, __nv_bfloat16* __restrict__ Clg,
    int M, int N, int K)
{
    extern __shared__ __nv_bfloat16 sm[];
    const int tid  = threadIdx.x;
    const int lane = tid & 31;
    const int wid  = tid >> 5;
    const int g    = lane >> 2;
    const int q    = lane & 3;
    const int m0   = (wid & 3) * 32;
    const int n0   = (wid >> 2) * 64;
    const int bRow = blockIdx.y * 128;
    const int bCol = blockIdx.x * 128;

    const int lrow = tid >> 2;
    const int lc8  = (tid & 3) * 8;

    const uint32_t a_row  = m0 + (lane & 15);
    const uint32_t a_koff = (lane >> 4) * 8;
    const uint32_t b_row  = n0 + (lane & 7) + ((lane >> 4) * 8);
    const uint32_t b_koff = ((lane >> 3) & 1) * 8;
    const uint32_t smem_u32 = (uint32_t)__cvta_generic_to_shared(sm);

    float c[2][8][4];
#pragma unroll
    for (int m = 0; m < 2; m++)
#pragma unroll
        for (int n = 0; n < 8; n++)
#pragma unroll
            for (int r = 0; r < 4; r++) c[m][n][r] = 0.f;

    const int NT = K / 32;

    auto issue = [&](int t, int stg) {
        const int k0 = t * 32;
        __nv_bfloat16* s = sm + stg * G_STAGE;
        const size_t aoff0 = (size_t)(bRow + lrow) * K + k0 + lc8;
        const size_t aoff1 = (size_t)(bRow + lrow + 64) * K + k0 + lc8;
        const size_t boff0 = (size_t)(bCol + lrow) * K + k0 + lc8;
        const size_t boff1 = (size_t)(bCol + lrow + 64) * K + k0 + lc8;
        cp16(s + G_AH + lrow * GST + lc8,        Ahg + aoff0);
        cp16(s + G_AH + (lrow + 64) * GST + lc8, Ahg + aoff1);
        cp16(s + G_AL + lrow * GST + lc8,        Alg + aoff0);
        cp16(s + G_AL + (lrow + 64) * GST + lc8, Alg + aoff1);
        cp16(s + G_BH + lrow * GST + lc8,        Bhg + boff0);
        cp16(s + G_BH + (lrow + 64) * GST + lc8, Bhg + boff1);
        cp16(s + G_BL + lrow * GST + lc8,        Blg + boff0);
        cp16(s + G_BL + (lrow + 64) * GST + lc8, Blg + boff1);
    };

    issue(0, 0);
    cp_commit();

    for (int t = 0; t < NT; ++t) {
        cp_wait<0>();          // stage t&1 landed (issued last iter, overlapped)
        __syncthreads();       // also orders prior reads of stage (t+1)&1
        if (t + 1 < NT) { issue(t + 1, (t + 1) & 1); cp_commit(); }

        const uint32_t sb = smem_u32 + ((t & 1) * G_STAGE) * 2;
#pragma unroll
        for (int kk = 0; kk < 2; kk++) {
            uint32_t ah[2][4], al[2][4];
            const uint32_t aoff = sb + (G_AH + a_row * GST + kk * 16 + a_koff) * 2;
            ldsm4(ah[0], aoff);
            ldsm4(ah[1], aoff + 16 * GST * 2);
            const uint32_t aloff = aoff + (G_AL - G_AH) * 2;
            ldsm4(al[0], aloff);
            ldsm4(al[1], aloff + 16 * GST * 2);

            uint32_t bh[8][2], bl[8][2];
#pragma unroll
            for (int p = 0; p < 4; p++) {
                uint32_t t4[4];
                const uint32_t boff = sb + (G_BH + (b_row + p * 16) * GST + kk * 16 + b_koff) * 2;
                ldsm4(t4, boff);
                bh[2 * p][0] = t4[0]; bh[2 * p][1] = t4[1];
                bh[2 * p + 1][0] = t4[2]; bh[2 * p + 1][1] = t4[3];
                ldsm4(t4, boff + (G_BL - G_BH) * 2);
                bl[2 * p][0] = t4[0]; bl[2 * p][1] = t4[1];
                bl[2 * p + 1][0] = t4[2]; bl[2 * p + 1][1] = t4[3];
            }
#pragma unroll
            for (int n = 0; n < 8; n++)
#pragma unroll
                for (int m = 0; m < 2; m++)
                    mma_bf16(c[m][n], ah[m], bh[n]);
#pragma unroll
            for (int n = 0; n < 8; n++)
#pragma unroll
                for (int m = 0; m < 2; m++)
                    mma_bf16(c[m][n], al[m], bh[n]);
#pragma unroll
            for (int n = 0; n < 8; n++)
#pragma unroll
                for (int m = 0; m < 2; m++)
                    mma_bf16(c[m][n], ah[m], bl[n]);
        }
    }

    // epilogue
#pragma unroll
    for (int m = 0; m < 2; m++) {
#pragma unroll
        for (int n = 0; n < 8; n++) {
            const int row = bRow + m0 + m * 16 + g;
            const int col = bCol + n0 + n * 8 + 2 * q;
#pragma unroll
            for (int half = 0; half < 2; half++) {
                const int r = row + half * 8;
                float v0 = c[m][n][half * 2 + 0];
                float v1 = c[m][n][half * 2 + 1];
                if (HAS_BIAS) { v0 += bias[col]; v1 += bias[col + 1]; }
                if (SPLIT_OUT) {
                    uint32_t hp, lp;
                    split2(v0, v1, hp, lp);
                    *reinterpret_cast<uint32_t*>(&Chg[(size_t)r * N + col]) = hp;
                    *reinterpret_cast<uint32_t*>(&Clg[(size_t)r * N + col]) = lp;
                } else {
                    float2 w; w.x = v0; w.y = v1;
                    *reinterpret_cast<float2*>(&Cf[(size_t)r * N + col]) = w;
                }
            }
        }
    }
}

// ---------------- split-bf16 causal flash attention --------------------------
// 256 thr (8 warps), 128q x 64k tiles. cp.async K/V double-buffer; V row-major
// + ldmatrix.trans; scale folded into exp; P split in registers.
// LPT scheduling: heavy (large-qt) tiles get the lowest blockIdx.
#define FST 72
#define FQ_E  (128 * FST)            // 9216 elems per Q array
#define FKV_E (64 * FST)             // 4608 elems per K/V array
#define E_QH 0
#define E_QL FQ_E
#define E_KV(stage) (2 * FQ_E + (stage) * 4 * FKV_E)
#define E_KH 0
#define E_KL FKV_E
#define E_VH (2 * FKV_E)
#define E_VL (3 * FKV_E)
#define FLASH_SMEM ((2 * FQ_E + 8 * FKV_E) * 2)   // 110592 bytes

__global__ __launch_bounds__(256, 2) void flash_sp(
    const __nv_bfloat16* __restrict__ qkvh,
    const __nv_bfloat16* __restrict__ qkvl,
    __nv_bfloat16* __restrict__ Oh, __nv_bfloat16* __restrict__ Ol)
{
    extern __shared__ __nv_bfloat16 fsm[];

    const int tid  = threadIdx.x;
    const int lane = tid & 31;
    const int wid  = tid >> 5;
    const int g    = lane >> 2;
    const int q    = lane & 3;
    const int qt   = gridDim.x - 1 - blockIdx.x;   // LPT: big tiles first
    const int b    = blockIdx.y >> 4;
    const int h    = blockIdx.y & 15;
    const int q0   = qt * 128;
    const int rl0  = wid * 16 + g;       // 0..127
    const int rl1  = rl0 + 8;

    // ldmatrix per-lane address components (element units)
    const uint32_t qa_row  = wid * 16 + (lane & 15);
    const uint32_t qa_koff = (lane >> 4) * 8;
    const uint32_t kb_row  = (lane & 7) + ((lane >> 4) * 8);   // K: rows over n
    const uint32_t kb_koff = ((lane >> 3) & 1) * 8;
    const uint32_t vt_row  = (lane & 7) + (((lane >> 3) & 1) * 8);  // V trans: rows over k
    const uint32_t vt_col  = (lane >> 4) * 8;
    const uint32_t fbase = (uint32_t)__cvta_generic_to_shared(fsm);

    // ---- async loaders ----
    auto issue_q = [&]() {
#pragma unroll
        for (int l = 0; l < 4; l++) {
            const int idx = tid + l * 256;   // 0..1023
            const int r = idx >> 3;          // 0..127
            const int c8 = (idx & 7) * 8;
            const size_t off = (size_t)(b * TT + q0 + r) * QKV_COLS + h * HDIM + c8;
            cp16(fsm + E_QH + r * FST + c8, qkvh + off);
            cp16(fsm + E_QL + r * FST + c8, qkvl + off);
        }
    };
    auto issue_kv = [&](int kt, int stage) {
        __nv_bfloat16* s = fsm + E_KV(stage);
#pragma unroll
        for (int l = 0; l < 2; l++) {
            const int idx = tid + l * 256;   // 0..511
            const int r = idx >> 3;          // 0..63
            const int c8 = (idx & 7) * 8;
            const size_t base = (size_t)(b * TT + kt * 64 + r) * QKV_COLS + h * HDIM + c8;
            cp16(s + E_KH + r * FST + c8, qkvh + base + DD);
            cp16(s + E_KL + r * FST + c8, qkvl + base + DD);
            cp16(s + E_VH + r * FST + c8, qkvh + base + 2 * DD);
            cp16(s + E_VL + r * FST + c8, qkvl + base + 2 * DD);
        }
    };

    const int ktmax = 2 * qt + 1;        // >= 1 always

    issue_q();
    issue_kv(0, 0);
    cp_commit();
    issue_kv(1, 1);
    cp_commit();

    float m0r = -1e30f, m1r = -1e30f, l0r = 0.f, l1r = 0.f;
    float o[8][4];
#pragma unroll
    for (int j = 0; j < 8; j++)
#pragma unroll
        for (int r = 0; r < 4; r++) o[j][r] = 0.f;

    for (int kt = 0; kt <= ktmax; kt++) {
        if (kt < ktmax) cp_wait<1>(); else cp_wait<0>();
        __syncthreads();

        const int stage = kt & 1;
        const uint32_t kvb = fbase + E_KV(stage) * 2;
        const uint32_t kh_b = kvb;
        const uint32_t vh_b = kvb + E_VH * 2;

        // S = Q K^T (hh + lh + hl) via ldmatrix
        float s[8][4];
#pragma unroll
        for (int j = 0; j < 8; j++)
#pragma unroll
            for (int r = 0; r < 4; r++) s[j][r] = 0.f;

#pragma unroll
        for (int kk = 0; kk < 4; kk++) {
            uint32_t qh[4], ql[4];
            const uint32_t qoff = fbase + (qa_row * FST + kk * 16 + qa_koff) * 2;
            ldsm4(qh, qoff);
            ldsm4(ql, qoff + FQ_E * 2);
            uint32_t kh2[8][2], kl2[8][2];
#pragma unroll
            for (int p = 0; p < 4; p++) {
                uint32_t t4[4];
                const uint32_t koff = kh_b + ((kb_row + p * 16) * FST + kk * 16 + kb_koff) * 2;
                ldsm4(t4, koff);
                kh2[2 * p][0] = t4[0]; kh2[2 * p][1] = t4[1];
                kh2[2 * p + 1][0] = t4[2]; kh2[2 * p + 1][1] = t4[3];
                ldsm4(t4, koff + FKV_E * 2);
                kl2[2 * p][0] = t4[0]; kl2[2 * p][1] = t4[1];
                kl2[2 * p + 1][0] = t4[2]; kl2[2 * p + 1][1] = t4[3];
            }
#pragma unroll
            for (int j = 0; j < 8; j++) mma_bf16(s[j], qh, kh2[j]);
#pragma unroll
            for (int j = 0; j < 8; j++) mma_bf16(s[j], ql, kh2[j]);
#pragma unroll
            for (int j = 0; j < 8; j++) mma_bf16(s[j], qh, kl2[j]);
        }

        if (kt >= 2 * qt) {   // diagonal region: elementwise causal mask
            const int coff = kt * 64 - q0;
#pragma unroll
            for (int j = 0; j < 8; j++) {
                const int c = coff + j * 8 + 2 * q;
                if (c     > rl0) s[j][0] = -1e30f;
                if (c + 1 > rl0) s[j][1] = -1e30f;
                if (c     > rl1) s[j][2] = -1e30f;
                if (c + 1 > rl1) s[j][3] = -1e30f;
            }
        }

        // online softmax (scale 1/8 folded into exp args; exact pow2)
        {
            float tm = -1e30f;
#pragma unroll
            for (int j = 0; j < 8; j++) tm = fmaxf(tm, fmaxf(s[j][0], s[j][1]));
            tm = fmaxf(tm, __shfl_xor_sync(0xffffffffu, tm, 1));
            tm = fmaxf(tm, __shfl_xor_sync(0xffffffffu, tm, 2));
            const float mn = fmaxf(m0r, tm);
            const float corr = __expf((m0r - mn) * 0.125f);
            m0r = mn;
            float rs = 0.f;
#pragma unroll
            for (int j = 0; j < 8; j++) {
                s[j][0] = __expf((s[j][0] - mn) * 0.125f); rs += s[j][0];
                s[j][1] = __expf((s[j][1] - mn) * 0.125f); rs += s[j][1];
            }
            rs += __shfl_xor_sync(0xffffffffu, rs, 1);
            rs += __shfl_xor_sync(0xffffffffu, rs, 2);
            l0r = l0r * corr + rs;
#pragma unroll
            for (int j = 0; j < 8; j++) { o[j][0] *= corr; o[j][1] *= corr; }
        }
        {
            float tm = -1e30f;
#pragma unroll
            for (int j = 0; j < 8; j++) tm = fmaxf(tm, fmaxf(s[j][2], s[j][3]));
            tm = fmaxf(tm, __shfl_xor_sync(0xffffffffu, tm, 1));
            tm = fmaxf(tm, __shfl_xor_sync(0xffffffffu, tm, 2));
            const float mn = fmaxf(m1r, tm);
            const float corr = __expf((m1r - mn) * 0.125f);
            m1r = mn;
            float rs = 0.f;
#pragma unroll
            for (int j = 0; j < 8; j++) {
                s[j][2] = __expf((s[j][2] - mn) * 0.125f); rs += s[j][2];
                s[j][3] = __expf((s[j][3] - mn) * 0.125f); rs += s[j][3];
            }
            rs += __shfl_xor_sync(0xffffffffu, rs, 1);
            rs += __shfl_xor_sync(0xffffffffu, rs, 2);
            l1r = l1r * corr + rs;
#pragma unroll
            for (int j = 0; j < 8; j++) { o[j][2] *= corr; o[j][3] *= corr; }
        }

        // O += P V : P split in registers; V via ldmatrix.trans (row-major smem)
#pragma unroll
        for (int kk = 0; kk < 4; kk++) {
            uint32_t pa_h[4], pa_l[4];
            split2(s[2 * kk][0],     s[2 * kk][1],     pa_h[0], pa_l[0]);
            split2(s[2 * kk][2],     s[2 * kk][3],     pa_h[1], pa_l[1]);
            split2(s[2 * kk + 1][0], s[2 * kk + 1][1], pa_h[2], pa_l[2]);
            split2(s[2 * kk + 1][2], s[2 * kk + 1][3], pa_h[3], pa_l[3]);

            uint32_t vh2[8][2], vl2[8][2];
#pragma unroll
            for (int p = 0; p < 4; p++) {
                uint32_t t4[4];
                const uint32_t voff = vh_b + ((kk * 16 + vt_row) * FST + p * 16 + vt_col) * 2;
                ldsm4t(t4, voff);
                vh2[2 * p][0] = t4[0]; vh2[2 * p][1] = t4[1];
                vh2[2 * p + 1][0] = t4[2]; vh2[2 * p + 1][1] = t4[3];
                ldsm4t(t4, voff + FKV_E * 2);
                vl2[2 * p][0] = t4[0]; vl2[2 * p][1] = t4[1];
                vl2[2 * p + 1][0] = t4[2]; vl2[2 * p + 1][1] = t4[3];
            }
#pragma unroll
            for (int j = 0; j < 8; j++) mma_bf16(o[j], pa_h, vh2[j]);
#pragma unroll
            for (int j = 0; j < 8; j++) mma_bf16(o[j], pa_l, vh2[j]);
#pragma unroll
            for (int j = 0; j < 8; j++) mma_bf16(o[j], pa_h, vl2[j]);
        }

        __syncthreads();   // all warps done with this stage before refill
        if (kt + 2 <= ktmax) {
            issue_kv(kt + 2, stage);
            cp_commit();
        }
    }

    // epilogue: normalize, split, store
    const float inv0 = 1.0f / l0r;
    const float inv1 = 1.0f / l1r;
#pragma unroll
    for (int j = 0; j < 8; j++) {
        const int col = h * HDIM + j * 8 + 2 * q;
#pragma unroll
        for (int half = 0; half < 2; half++) {
            const int r = (half == 0) ? rl0 : rl1;
            const float inv = (half == 0) ? inv0 : inv1;
            const float v0 = o[j][half * 2 + 0] * inv;
            const float v1 = o[j][half * 2 + 1] * inv;
            uint32_t hp, lp;
            split2(v0, v1, hp, lp);
            const size_t off = (size_t)(b * TT + q0 + r) * DD + col;
            *reinterpret_cast<uint32_t*>(&Oh[off]) = hp;
            *reinterpret_cast<uint32_t*>(&Ol[off]) = lp;
        }
    }
}

// ---------------------------------------------------------------------------
extern "C" void kernel_launch(void* const* d_in, const int* in_sizes, int n_in,
                              void* d_out, int out_size)
{
    const float* x     = (const float*)d_in[0];
    const float* Wqkv  = (const float*)d_in[1];
    const float* Wproj = (const float*)d_in[2];
    const float* bproj = (const float*)d_in[3];
    float* out = (float*)d_out;

    __nv_bfloat16 *xh, *xl, *wqh, *wql, *wph, *wpl, *qkvh, *qkvl, *ah, *al;
    cudaGetSymbolAddress((void**)&xh,   g_xh);
    cudaGetSymbolAddress((void**)&xl,   g_xl);
    cudaGetSymbolAddress((void**)&wqh,  g_wqh);
    cudaGetSymbolAddress((void**)&wql,  g_wql);
    cudaGetSymbolAddress((void**)&wph,  g_wph);
    cudaGetSymbolAddress((void**)&wpl,  g_wpl);
    cudaGetSymbolAddress((void**)&qkvh, g_qkvh);
    cudaGetSymbolAddress((void**)&qkvl, g_qkvl);
    cudaGetSymbolAddress((void**)&ah,   g_ah);
    cudaGetSymbolAddress((void**)&al,   g_al);

    cudaFuncSetAttribute(gemm_sp<true, false>,
                         cudaFuncAttributeMaxDynamicSharedMemorySize, GEMM_SMEM);
    cudaFuncSetAttribute(gemm_sp<false, true>,
                         cudaFuncAttributeMaxDynamicSharedMemorySize, GEMM_SMEM);
    cudaFuncSetAttribute(flash_sp,
                         cudaFuncAttributeMaxDynamicSharedMemorySize, FLASH_SMEM);

    // splits
    split_kernel<<<(MROWS * DD / 4 + 255) / 256, 256>>>(x, xh, xl, MROWS * DD / 4);
    split_kernel<<<(QKV_COLS * DD / 4 + 255) / 256, 256>>>(Wqkv, wqh, wql, QKV_COLS * DD / 4);
    split_kernel<<<(DD * DD / 4 + 255) / 256, 256>>>(Wproj, wph, wpl, DD * DD / 4);

    // 1) QKV projection (split output for attention)
    {
        dim3 grid(QKV_COLS / 128, MROWS / 128);
        gemm_sp<true, false><<<grid, 256, GEMM_SMEM>>>(
            xh, xl, wqh, wql, nullptr, nullptr, qkvh, qkvl, MROWS, QKV_COLS, DD);
    }
    // 2) causal flash attention (128q x 64k tiles, LPT order)
    {
        dim3 grid(TT / 128, BB * HH);
        flash_sp<<<grid, 256, FLASH_SMEM>>>(qkvh, qkvl, ah, al);
    }
    // 3) output projection (fp32 out, bias)
    {
        dim3 grid(DD / 128, MROWS / 128);
        gemm_sp<false, true><<<grid, 256, GEMM_SMEM>>>(
            ah, al, wph, wpl, bproj, out, nullptr, nullptr, MROWS, DD, DD);
    }
}